// round 12
// baseline (speedup 1.0000x reference)
#include <cuda_runtime.h>
#include <cuda_bf16.h>
#include <cuda_pipeline_primitives.h>
#include <mma.h>
#include <math.h>

using namespace nvcuda;

// ---------------------------------------------------------------------------
// WITT AdaLN Swin block. wmma bf16 GEMMs + FMA-pipe softmax attention.
// B=16, H=W=64, C=256, NH=8, HD=32, WS=8, SS=4, N=64, NWIN=64, MLP_H=1024.
// ---------------------------------------------------------------------------

#define TOK 65536
typedef __nv_bfloat16 bf16;

__device__ __align__(16) float g_ada  [16 * 1536];
__device__ __align__(16) bf16  g_wb   [786432];             // bf16 weights [K,N]
__device__ __align__(16) bf16  g_hwinh[(size_t)TOK * 256];
__device__ __align__(16) bf16  g_qkvh [(size_t)TOK * 768];
__device__ __align__(16) bf16  g_attnh[(size_t)TOK * 256];
__device__ __align__(16) float g_x1   [(size_t)TOK * 256];
__device__ __align__(16) bf16  g_h2h  [(size_t)TOK * 256];
__device__ __align__(16) bf16  g_mlph [(size_t)TOK * 1024];

#define WOFF_QKV  0
#define WOFF_PROJ 196608
#define WOFF_FC1  262144
#define WOFF_FC2  524288

__device__ __forceinline__ uint32_t packbf(float a, float b) {
    __nv_bfloat162 t = __floats2bfloat162_rn(a, b);
    return *reinterpret_cast<uint32_t*>(&t);
}

// exp on the FMA pipe (no MUFU). Valid for x <= ~2; clamps very negative x.
__device__ __forceinline__ float fexp(float x) {
    x = fmaxf(x, -80.0f);
    float t = fmaf(x, 1.4426950408889634f, 12582912.0f);
    float n = t - 12582912.0f;                       // round(x * log2e)
    float r = fmaf(n, -0.6931471805599453f, x);      // r in [-0.347, 0.347]
    float p = 8.3333337e-3f;
    p = fmaf(p, r, 4.1666668e-2f);
    p = fmaf(p, r, 1.6666667e-1f);
    p = fmaf(p, r, 5.0e-1f);
    p = fmaf(p, r, 1.0f);
    p = fmaf(p, r, 1.0f);
    float sc = __int_as_float(((int)n + 127) << 23);
    return p * sc;
}

// ---------------------------------------------------------------------------
// all-weights fp32 -> bf16 (single launch). 196608 chunks of 4 floats.
// ---------------------------------------------------------------------------
__global__ void cvt_all_kernel(const float* __restrict__ w_qkv,
                               const float* __restrict__ w_proj,
                               const float* __restrict__ w_fc1,
                               const float* __restrict__ w_fc2) {
    int i = blockIdx.x * blockDim.x + threadIdx.x;
    const float* src; int off;
    if (i < 49152)       { src = w_qkv;  off = 0; }
    else if (i < 65536)  { src = w_proj; off = 49152; }
    else if (i < 131072) { src = w_fc1;  off = 65536; }
    else                 { src = w_fc2;  off = 131072; }
    float4 v = __ldg((const float4*)src + (i - off));
    uint2 u;
    u.x = packbf(v.x, v.y);
    u.y = packbf(v.z, v.w);
    *((uint2*)g_wb + i) = u;
}

// ---------------------------------------------------------------------------
// ada = silu(cond) @ w_ada + b_ada   [16,1536]
// ---------------------------------------------------------------------------
__global__ void ada_kernel(const float* __restrict__ cond,
                           const float* __restrict__ w_ada,
                           const float* __restrict__ b_ada) {
    __shared__ float sc[256];
    int b = blockIdx.x, t = threadIdx.x;
    float v = cond[b * 256 + t];
    sc[t] = v / (1.0f + expf(-v));
    __syncthreads();
    for (int j = t; j < 1536; j += 256) {
        float acc = b_ada[j];
        #pragma unroll 4
        for (int i = 0; i < 256; i++) acc = fmaf(sc[i], __ldg(&w_ada[i * 1536 + j]), acc);
        g_ada[b * 1536 + j] = acc;
    }
}

// ---------------------------------------------------------------------------
// LN + AdaLN -> bf16. PASS 0: roll(-4,-4)+window partition; PASS 1: plain.
// ---------------------------------------------------------------------------
template <int PASS>
__global__ void ln_mod_kernel(const float* __restrict__ xin,
                              const float* __restrict__ gamma,
                              const float* __restrict__ beta) {
    int gw   = (blockIdx.x * blockDim.x + threadIdx.x) >> 5;
    int lane = threadIdx.x & 31;
    int b = gw >> 12;

    const float* src;
    bf16* dst;
    if (PASS == 0) {
        int t = gw & 63, widx = (gw >> 6) & 63;
        int wh = (widx >> 3) & 7, ww = widx & 7;
        int sr  = (wh * 8 + (t >> 3) + 4) & 63;
        int sc2 = (ww * 8 + (t & 7) + 4) & 63;
        src = xin + ((size_t)(b * 4096 + sr * 64 + sc2)) * 256;
        dst = g_hwinh + (size_t)gw * 256;
    } else {
        src = g_x1 + (size_t)gw * 256;
        dst = g_h2h + (size_t)gw * 256;
    }

    float4 v0 = *(const float4*)(src + lane * 8);
    float4 v1 = *(const float4*)(src + lane * 8 + 4);
    float e[8] = {v0.x, v0.y, v0.z, v0.w, v1.x, v1.y, v1.z, v1.w};

    float s = 0.f, q = 0.f;
    #pragma unroll
    for (int j = 0; j < 8; j++) { s += e[j]; q += e[j] * e[j]; }
    #pragma unroll
    for (int off = 16; off > 0; off >>= 1) {
        s += __shfl_xor_sync(0xffffffffu, s, off);
        q += __shfl_xor_sync(0xffffffffu, q, off);
    }
    float mean = s * (1.0f / 256.0f);
    float var  = q * (1.0f / 256.0f) - mean * mean;
    float rstd = rsqrtf(var + 1e-5f);

    const float* scl = g_ada + b * 1536 + (PASS == 0 ? 256 : 1024);
    const float* sft = g_ada + b * 1536 + (PASS == 0 ? 0   : 768);

    int ch = lane * 8;
    float o[8];
    #pragma unroll
    for (int j = 0; j < 8; j++) {
        float y = (e[j] - mean) * rstd * __ldg(&gamma[ch + j]) + __ldg(&beta[ch + j]);
        o[j] = y * (1.0f + scl[ch + j]) + sft[ch + j];
    }
    uint4 u;
    u.x = packbf(o[0], o[1]); u.y = packbf(o[2], o[3]);
    u.z = packbf(o[4], o[5]); u.w = packbf(o[6], o[7]);
    *(uint4*)(dst + ch) = u;
}

// ---------------------------------------------------------------------------
// Attention per (window, head): 64 threads, FMA-pipe softmax, float4 smem.
// ---------------------------------------------------------------------------
__global__ void attn_kernel(const float* __restrict__ rel_bias) {
    __shared__ float4 ks4[64][9];
    __shared__ float4 vs4[64][9];
    __shared__ float  sb[225];
    __shared__ int    idm_s[64];
    int widx = blockIdx.x;
    int h    = blockIdx.y;
    int n    = threadIdx.x;

    for (int i = n; i < 225; i += 64) sb[i] = __ldg(&rel_bias[i * 8 + h]);

    int wh = (widx >> 3) & 7, ww = widx & 7;
    {   // region id of this thread's token (also stored for others to read)
        int ii = n >> 3, jj = n & 7;
        int rv = wh * 8 + ii, cv = ww * 8 + jj;
        idm_s[n] = (rv < 56 ? 0 : (rv < 60 ? 1 : 2)) * 3 +
                   (cv < 56 ? 0 : (cv < 60 ? 1 : 2));
    }

    const bf16* rowp = g_qkvh + (size_t)widx * 64 * 768 + (size_t)n * 768 + h * 32;
    const float scale = 0.17677669529663687f;
    float q[32];
    #pragma unroll
    for (int j = 0; j < 4; j++) {
        uint4 uq = *(const uint4*)(rowp + j * 8);
        uint4 uk = *(const uint4*)(rowp + 256 + j * 8);
        uint4 uv = *(const uint4*)(rowp + 512 + j * 8);
        const uint32_t* pq = &uq.x;
        const uint32_t* pk = &uk.x;
        const uint32_t* pv = &uv.x;
        float kf[8], vf[8];
        #pragma unroll
        for (int p = 0; p < 4; p++) {
            float2 fq = __bfloat1622float2(*(const __nv_bfloat162*)&pq[p]);
            q[j * 8 + p * 2]     = fq.x * scale;
            q[j * 8 + p * 2 + 1] = fq.y * scale;
            float2 fk = __bfloat1622float2(*(const __nv_bfloat162*)&pk[p]);
            kf[p * 2] = fk.x; kf[p * 2 + 1] = fk.y;
            float2 fv = __bfloat1622float2(*(const __nv_bfloat162*)&pv[p]);
            vf[p * 2] = fv.x; vf[p * 2 + 1] = fv.y;
        }
        ks4[n][j * 2]     = make_float4(kf[0], kf[1], kf[2], kf[3]);
        ks4[n][j * 2 + 1] = make_float4(kf[4], kf[5], kf[6], kf[7]);
        vs4[n][j * 2]     = make_float4(vf[0], vf[1], vf[2], vf[3]);
        vs4[n][j * 2 + 1] = make_float4(vf[4], vf[5], vf[6], vf[7]);
    }
    __syncthreads();

    int i1 = n >> 3, j1 = n & 7;
    int idn = idm_s[n];

    float o[32];
    #pragma unroll
    for (int d = 0; d < 32; d++) o[d] = 0.f;
    float sum = 0.f;

    for (int m = 0; m < 64; m++) {
        float s = 0.f;
        #pragma unroll
        for (int j = 0; j < 8; j++) {
            float4 kv = ks4[m][j];
            s = fmaf(q[j * 4 + 0], kv.x, s);
            s = fmaf(q[j * 4 + 1], kv.y, s);
            s = fmaf(q[j * 4 + 2], kv.z, s);
            s = fmaf(q[j * 4 + 3], kv.w, s);
        }
        int i2 = m >> 3, j2 = m & 7;
        s += sb[(i1 - i2 + 7) * 15 + (j1 - j2 + 7)];
        if (idm_s[m] != idn) s -= 100.0f;
        float p = fexp(s);
        sum += p;
        #pragma unroll
        for (int j = 0; j < 8; j++) {
            float4 vv = vs4[m][j];
            o[j * 4 + 0] = fmaf(p, vv.x, o[j * 4 + 0]);
            o[j * 4 + 1] = fmaf(p, vv.y, o[j * 4 + 1]);
            o[j * 4 + 2] = fmaf(p, vv.z, o[j * 4 + 2]);
            o[j * 4 + 3] = fmaf(p, vv.w, o[j * 4 + 3]);
        }
    }
    float inv = 1.0f / sum;

    bf16* outp = g_attnh + (size_t)(widx * 64 + n) * 256 + h * 32;
    #pragma unroll
    for (int j = 0; j < 4; j++) {
        uint4 u;
        u.x = packbf(o[j*8+0]*inv, o[j*8+1]*inv);
        u.y = packbf(o[j*8+2]*inv, o[j*8+3]*inv);
        u.z = packbf(o[j*8+4]*inv, o[j*8+5]*inv);
        u.w = packbf(o[j*8+6]*inv, o[j*8+7]*inv);
        *(uint4*)(outp + j * 8) = u;
    }
}

// ---------------------------------------------------------------------------
// wmma bf16 GEMM: CTA 128x128, 4 warps (warp tile 64x64, 4x4 frags),
// BK=32, 4-stage cp.async pipeline, fused epilogue via smem roundtrip.
// MODE 0: g_qkvh     = bf16(A @ W + b)            N=768  K=256
// MODE 1: g_x1[perm] = x[perm] + gm*(A @ W + b)   N=256  K=256
// MODE 2: g_mlph     = bf16(gelu(A @ W + b))      N=1024 K=256
// MODE 3: out        = g_x1 + gp*(A @ W + b)      N=256  K=1024
// ---------------------------------------------------------------------------
#define AS_STR 40
#define BS_STR 136
#define STAGE_B (128 * AS_STR * 2 + 32 * BS_STR * 2)   // 18944
#define GEMM_SMEM (4 * STAGE_B)                         // 75776

template <int MODE>
__global__ __launch_bounds__(128, 2)
void gemm_bf16(const float* __restrict__ bias,
               const float* __restrict__ xres,
               float* __restrict__ outp) {
    constexpr int K = (MODE == 3) ? 1024 : 256;
    constexpr int N = (MODE == 0) ? 768 : (MODE == 2) ? 1024 : 256;
    constexpr int NIT = K / 32;
    const bf16* A = (MODE == 0) ? g_hwinh : (MODE == 1) ? g_attnh
                  : (MODE == 2) ? g_h2h   : g_mlph;
    const bf16* W = g_wb + ((MODE == 0) ? WOFF_QKV : (MODE == 1) ? WOFF_PROJ
                         : (MODE == 2) ? WOFF_FC1 : WOFF_FC2);

    extern __shared__ char dsm[];
    int tid = threadIdx.x;
    int wid = tid >> 5;
    int wm = wid & 1;
    int wn = wid >> 1;
    int bm = blockIdx.y * 128, bn = blockIdx.x * 128;

    wmma::fragment<wmma::accumulator, 16, 16, 16, float> acc[4][4];
    #pragma unroll
    for (int mf = 0; mf < 4; mf++)
        #pragma unroll
        for (int nf = 0; nf < 4; nf++)
            wmma::fill_fragment(acc[mf][nf], 0.0f);

    const bf16* Abase = A + (size_t)bm * K;

    auto issue = [&](int it) {
        int buf = it & 3;
        bf16* As = (bf16*)(dsm + buf * STAGE_B);
        bf16* Bs = (bf16*)(dsm + buf * STAGE_B + 128 * AS_STR * 2);
        int k0 = it * 32;
        #pragma unroll
        for (int t = 0; t < 4; t++) {
            int idx = tid + t * 128;
            int r = idx >> 2, c = (idx & 3) * 8;
            __pipeline_memcpy_async(As + r * AS_STR + c,
                                    Abase + (size_t)r * K + k0 + c, 16);
        }
        #pragma unroll
        for (int t = 0; t < 4; t++) {
            int idx = tid + t * 128;
            int r = idx >> 4, c = (idx & 15) * 8;
            __pipeline_memcpy_async(Bs + r * BS_STR + c,
                                    W + (size_t)(k0 + r) * N + bn + c, 16);
        }
        __pipeline_commit();
    };

    issue(0);
    if (NIT > 1) issue(1);
    if (NIT > 2) issue(2);

    for (int it = 0; it < NIT; it++) {
        if (NIT - 1 - it >= 2)      __pipeline_wait_prior(2);
        else if (NIT - 1 - it == 1) __pipeline_wait_prior(1);
        else                        __pipeline_wait_prior(0);
        __syncthreads();

        const bf16* As = (const bf16*)(dsm + (it & 3) * STAGE_B);
        const bf16* Bs = (const bf16*)(dsm + (it & 3) * STAGE_B + 128 * AS_STR * 2);
        #pragma unroll
        for (int kk = 0; kk < 32; kk += 16) {
            wmma::fragment<wmma::matrix_a, 16, 16, 16, bf16, wmma::row_major> af[4];
            wmma::fragment<wmma::matrix_b, 16, 16, 16, bf16, wmma::row_major> bf[4];
            #pragma unroll
            for (int mf = 0; mf < 4; mf++)
                wmma::load_matrix_sync(af[mf], As + (wm * 64 + mf * 16) * AS_STR + kk, AS_STR);
            #pragma unroll
            for (int nf = 0; nf < 4; nf++)
                wmma::load_matrix_sync(bf[nf], Bs + kk * BS_STR + wn * 64 + nf * 16, BS_STR);
            #pragma unroll
            for (int mf = 0; mf < 4; mf++)
                #pragma unroll
                for (int nf = 0; nf < 4; nf++)
                    wmma::mma_sync(acc[mf][nf], af[mf], bf[nf], acc[mf][nf]);
        }
        if (it + 3 < NIT) issue(it + 3);
    }
    __syncthreads();

    // ---- epilogue via smem roundtrip (alias stage buffers: 64KB fp32) ----
    float* epi = (float*)dsm;
    #pragma unroll
    for (int mf = 0; mf < 4; mf++)
        #pragma unroll
        for (int nf = 0; nf < 4; nf++)
            wmma::store_matrix_sync(epi + (wm * 64 + mf * 16) * 128 + wn * 64 + nf * 16,
                                    acc[mf][nf], 128, wmma::mem_row_major);
    __syncthreads();

    #pragma unroll
    for (int t = 0; t < 16; t++) {
        int ch = tid + t * 128;
        int r = ch >> 4;
        int c8 = (ch & 15) * 8;
        int col = bn + c8;
        int row = bm + r;
        float v[8];
        *(float4*)(v)     = *(const float4*)(epi + r * 128 + c8);
        *(float4*)(v + 4) = *(const float4*)(epi + r * 128 + c8 + 4);
        #pragma unroll
        for (int j = 0; j < 8; j++) v[j] += __ldg(&bias[col + j]);

        if (MODE == 0) {
            uint4 u;
            u.x = packbf(v[0], v[1]); u.y = packbf(v[2], v[3]);
            u.z = packbf(v[4], v[5]); u.w = packbf(v[6], v[7]);
            *(uint4*)(g_qkvh + (size_t)row * 768 + col) = u;
        } else if (MODE == 1) {
            int b = row >> 12, tt = row & 63, widx = (row >> 6) & 63;
            int wh = (widx >> 3) & 7, ww = widx & 7;
            int pr = (wh * 8 + (tt >> 3) + 4) & 63;
            int pc = (ww * 8 + (tt & 7) + 4) & 63;
            size_t prow = (size_t)(b * 4096 + pr * 64 + pc);
            const float* gm = g_ada + b * 1536 + 512;
            float o[8];
            #pragma unroll
            for (int j = 0; j < 8; j++)
                o[j] = __ldg(&xres[prow * 256 + col + j]) + gm[col + j] * v[j];
            *(float4*)(g_x1 + prow * 256 + col)     = *(float4*)(o);
            *(float4*)(g_x1 + prow * 256 + col + 4) = *(float4*)(o + 4);
        } else if (MODE == 2) {
            uint4 u;
            float o[8];
            #pragma unroll
            for (int j = 0; j < 8; j++)
                o[j] = 0.5f * v[j] * (1.0f + erff(v[j] * 0.70710678118654752f));
            u.x = packbf(o[0], o[1]); u.y = packbf(o[2], o[3]);
            u.z = packbf(o[4], o[5]); u.w = packbf(o[6], o[7]);
            *(uint4*)(g_mlph + (size_t)row * 1024 + col) = u;
        } else {
            int b = row >> 12;
            const float* gp = g_ada + b * 1536 + 1280;
            const float* x1 = g_x1 + (size_t)row * 256 + col;
            float o[8];
            #pragma unroll
            for (int j = 0; j < 8; j++)
                o[j] = x1[j] + gp[col + j] * v[j];
            *(float4*)(outp + (size_t)row * 256 + col)     = *(float4*)(o);
            *(float4*)(outp + (size_t)row * 256 + col + 4) = *(float4*)(o + 4);
        }
    }
}

// ---------------------------------------------------------------------------
extern "C" void kernel_launch(void* const* d_in, const int* in_sizes, int n_in,
                              void* d_out, int out_size) {
    const float* x       = (const float*)d_in[0];
    const float* cond    = (const float*)d_in[1];
    const float* norm1_g = (const float*)d_in[2];
    const float* norm1_b = (const float*)d_in[3];
    const float* w_qkv   = (const float*)d_in[4];
    const float* b_qkv   = (const float*)d_in[5];
    const float* rel_b   = (const float*)d_in[6];
    const float* w_proj  = (const float*)d_in[7];
    const float* b_proj  = (const float*)d_in[8];
    const float* norm2_g = (const float*)d_in[9];
    const float* norm2_b = (const float*)d_in[10];
    const float* w_fc1   = (const float*)d_in[11];
    const float* b_fc1   = (const float*)d_in[12];
    const float* w_fc2   = (const float*)d_in[13];
    const float* b_fc2   = (const float*)d_in[14];
    const float* w_ada   = (const float*)d_in[15];
    const float* b_ada   = (const float*)d_in[16];
    float* out = (float*)d_out;

    cudaFuncSetAttribute(gemm_bf16<0>, cudaFuncAttributeMaxDynamicSharedMemorySize, GEMM_SMEM);
    cudaFuncSetAttribute(gemm_bf16<1>, cudaFuncAttributeMaxDynamicSharedMemorySize, GEMM_SMEM);
    cudaFuncSetAttribute(gemm_bf16<2>, cudaFuncAttributeMaxDynamicSharedMemorySize, GEMM_SMEM);
    cudaFuncSetAttribute(gemm_bf16<3>, cudaFuncAttributeMaxDynamicSharedMemorySize, GEMM_SMEM);

    cvt_all_kernel<<<768, 256>>>(w_qkv, w_proj, w_fc1, w_fc2);
    ada_kernel<<<16, 256>>>(cond, w_ada, b_ada);
    ln_mod_kernel<0><<<8192, 256>>>(x, norm1_g, norm1_b);
    gemm_bf16<0><<<dim3(6, 512), 128, GEMM_SMEM>>>(b_qkv, nullptr, nullptr);
    attn_kernel<<<dim3(1024, 8), 64>>>(rel_b);
    gemm_bf16<1><<<dim3(2, 512), 128, GEMM_SMEM>>>(b_proj, x, nullptr);
    ln_mod_kernel<1><<<8192, 256>>>(nullptr, norm2_g, norm2_b);
    gemm_bf16<2><<<dim3(8, 512), 128, GEMM_SMEM>>>(b_fc1, nullptr, nullptr);
    gemm_bf16<3><<<dim3(2, 512), 128, GEMM_SMEM>>>(b_fc2, nullptr, out);
}

// round 13
// speedup vs baseline: 1.0057x; 1.0057x over previous
#include <cuda_runtime.h>
#include <cuda_bf16.h>
#include <cuda_pipeline_primitives.h>
#include <mma.h>
#include <math.h>

using namespace nvcuda;

// ---------------------------------------------------------------------------
// WITT AdaLN Swin block. wmma bf16 GEMMs + fused attention.
// B=16, H=W=64, C=256, NH=8, HD=32, WS=8, SS=4, N=64, NWIN=64, MLP_H=1024.
// ---------------------------------------------------------------------------

#define TOK 65536
typedef __nv_bfloat16 bf16;

__device__ __align__(16) float g_ada  [16 * 1536];
__device__ __align__(16) bf16  g_wb   [786432];             // bf16 weights [K,N]
__device__ __align__(16) bf16  g_hwinh[(size_t)TOK * 256];
__device__ __align__(16) bf16  g_qkvh [(size_t)TOK * 768];
__device__ __align__(16) bf16  g_attnh[(size_t)TOK * 256];
__device__ __align__(16) float g_x1   [(size_t)TOK * 256];
__device__ __align__(16) bf16  g_h2h  [(size_t)TOK * 256];
__device__ __align__(16) bf16  g_mlph [(size_t)TOK * 1024];

#define WOFF_QKV  0
#define WOFF_PROJ 196608
#define WOFF_FC1  262144
#define WOFF_FC2  524288

__device__ __forceinline__ uint32_t packbf(float a, float b) {
    __nv_bfloat162 t = __floats2bfloat162_rn(a, b);
    return *reinterpret_cast<uint32_t*>(&t);
}

// ---------------------------------------------------------------------------
// all-weights fp32 -> bf16 (single launch). 196608 chunks of 4 floats.
// ---------------------------------------------------------------------------
__global__ void cvt_all_kernel(const float* __restrict__ w_qkv,
                               const float* __restrict__ w_proj,
                               const float* __restrict__ w_fc1,
                               const float* __restrict__ w_fc2) {
    int i = blockIdx.x * blockDim.x + threadIdx.x;
    const float* src; int off;
    if (i < 49152)       { src = w_qkv;  off = 0; }
    else if (i < 65536)  { src = w_proj; off = 49152; }
    else if (i < 131072) { src = w_fc1;  off = 65536; }
    else                 { src = w_fc2;  off = 131072; }
    float4 v = __ldg((const float4*)src + (i - off));
    uint2 u;
    u.x = packbf(v.x, v.y);
    u.y = packbf(v.z, v.w);
    *((uint2*)g_wb + i) = u;
}

// ---------------------------------------------------------------------------
// ada = silu(cond) @ w_ada + b_ada   [16,1536]
// ---------------------------------------------------------------------------
__global__ void ada_kernel(const float* __restrict__ cond,
                           const float* __restrict__ w_ada,
                           const float* __restrict__ b_ada) {
    __shared__ float sc[256];
    int b = blockIdx.x, t = threadIdx.x;
    float v = cond[b * 256 + t];
    sc[t] = v / (1.0f + expf(-v));
    __syncthreads();
    for (int j = t; j < 1536; j += 256) {
        float acc = b_ada[j];
        #pragma unroll 4
        for (int i = 0; i < 256; i++) acc = fmaf(sc[i], __ldg(&w_ada[i * 1536 + j]), acc);
        g_ada[b * 1536 + j] = acc;
    }
}

// ---------------------------------------------------------------------------
// LN + AdaLN -> bf16. PASS 0: roll(-4,-4)+window partition; PASS 1: plain.
// ---------------------------------------------------------------------------
template <int PASS>
__global__ void ln_mod_kernel(const float* __restrict__ xin,
                              const float* __restrict__ gamma,
                              const float* __restrict__ beta) {
    int gw   = (blockIdx.x * blockDim.x + threadIdx.x) >> 5;
    int lane = threadIdx.x & 31;
    int b = gw >> 12;

    const float* src;
    bf16* dst;
    if (PASS == 0) {
        int t = gw & 63, widx = (gw >> 6) & 63;
        int wh = (widx >> 3) & 7, ww = widx & 7;
        int sr  = (wh * 8 + (t >> 3) + 4) & 63;
        int sc2 = (ww * 8 + (t & 7) + 4) & 63;
        src = xin + ((size_t)(b * 4096 + sr * 64 + sc2)) * 256;
        dst = g_hwinh + (size_t)gw * 256;
    } else {
        src = g_x1 + (size_t)gw * 256;
        dst = g_h2h + (size_t)gw * 256;
    }

    float4 v0 = *(const float4*)(src + lane * 8);
    float4 v1 = *(const float4*)(src + lane * 8 + 4);
    float e[8] = {v0.x, v0.y, v0.z, v0.w, v1.x, v1.y, v1.z, v1.w};

    float s = 0.f, q = 0.f;
    #pragma unroll
    for (int j = 0; j < 8; j++) { s += e[j]; q += e[j] * e[j]; }
    #pragma unroll
    for (int off = 16; off > 0; off >>= 1) {
        s += __shfl_xor_sync(0xffffffffu, s, off);
        q += __shfl_xor_sync(0xffffffffu, q, off);
    }
    float mean = s * (1.0f / 256.0f);
    float var  = q * (1.0f / 256.0f) - mean * mean;
    float rstd = rsqrtf(var + 1e-5f);

    const float* scl = g_ada + b * 1536 + (PASS == 0 ? 256 : 1024);
    const float* sft = g_ada + b * 1536 + (PASS == 0 ? 0   : 768);

    int ch = lane * 8;
    float o[8];
    #pragma unroll
    for (int j = 0; j < 8; j++) {
        float y = (e[j] - mean) * rstd * __ldg(&gamma[ch + j]) + __ldg(&beta[ch + j]);
        o[j] = y * (1.0f + scl[ch + j]) + sft[ch + j];
    }
    uint4 u;
    u.x = packbf(o[0], o[1]); u.y = packbf(o[2], o[3]);
    u.z = packbf(o[4], o[5]); u.w = packbf(o[6], o[7]);
    *(uint4*)(dst + ch) = u;
}

// ---------------------------------------------------------------------------
// Attention per (window, head): 64 threads, unnormalized softmax (__expf),
// float4 smem, 4-way split QK accumulation (breaks serial fma chain).
// ---------------------------------------------------------------------------
__global__ void attn_kernel(const float* __restrict__ rel_bias) {
    __shared__ float4 ks4[64][9];
    __shared__ float4 vs4[64][9];
    __shared__ float  sb[225];
    __shared__ int    idm_s[64];
    int widx = blockIdx.x;
    int h    = blockIdx.y;
    int n    = threadIdx.x;

    for (int i = n; i < 225; i += 64) sb[i] = __ldg(&rel_bias[i * 8 + h]);

    int wh = (widx >> 3) & 7, ww = widx & 7;
    {
        int ii = n >> 3, jj = n & 7;
        int rv = wh * 8 + ii, cv = ww * 8 + jj;
        idm_s[n] = (rv < 56 ? 0 : (rv < 60 ? 1 : 2)) * 3 +
                   (cv < 56 ? 0 : (cv < 60 ? 1 : 2));
    }

    const bf16* rowp = g_qkvh + (size_t)widx * 64 * 768 + (size_t)n * 768 + h * 32;
    const float scale = 0.17677669529663687f;
    float q[32];
    #pragma unroll
    for (int j = 0; j < 4; j++) {
        uint4 uq = *(const uint4*)(rowp + j * 8);
        uint4 uk = *(const uint4*)(rowp + 256 + j * 8);
        uint4 uv = *(const uint4*)(rowp + 512 + j * 8);
        const uint32_t* pq = &uq.x;
        const uint32_t* pk = &uk.x;
        const uint32_t* pv = &uv.x;
        float kf[8], vf[8];
        #pragma unroll
        for (int p = 0; p < 4; p++) {
            float2 fq = __bfloat1622float2(*(const __nv_bfloat162*)&pq[p]);
            q[j * 8 + p * 2]     = fq.x * scale;
            q[j * 8 + p * 2 + 1] = fq.y * scale;
            float2 fk = __bfloat1622float2(*(const __nv_bfloat162*)&pk[p]);
            kf[p * 2] = fk.x; kf[p * 2 + 1] = fk.y;
            float2 fv = __bfloat1622float2(*(const __nv_bfloat162*)&pv[p]);
            vf[p * 2] = fv.x; vf[p * 2 + 1] = fv.y;
        }
        ks4[n][j * 2]     = make_float4(kf[0], kf[1], kf[2], kf[3]);
        ks4[n][j * 2 + 1] = make_float4(kf[4], kf[5], kf[6], kf[7]);
        vs4[n][j * 2]     = make_float4(vf[0], vf[1], vf[2], vf[3]);
        vs4[n][j * 2 + 1] = make_float4(vf[4], vf[5], vf[6], vf[7]);
    }
    __syncthreads();

    int i1 = n >> 3, j1 = n & 7;
    int idn = idm_s[n];

    float o[32];
    #pragma unroll
    for (int d = 0; d < 32; d++) o[d] = 0.f;
    float sum = 0.f;

    for (int m = 0; m < 64; m++) {
        float s0 = 0.f, s1 = 0.f, s2 = 0.f, s3 = 0.f;
        #pragma unroll
        for (int j = 0; j < 2; j++) {
            float4 ka = ks4[m][j * 4 + 0];
            float4 kb = ks4[m][j * 4 + 1];
            float4 kc = ks4[m][j * 4 + 2];
            float4 kd = ks4[m][j * 4 + 3];
            s0 = fmaf(q[j*16 + 0], ka.x, s0); s0 = fmaf(q[j*16 + 1], ka.y, s0);
            s1 = fmaf(q[j*16 + 2], ka.z, s1); s1 = fmaf(q[j*16 + 3], ka.w, s1);
            s2 = fmaf(q[j*16 + 4], kb.x, s2); s2 = fmaf(q[j*16 + 5], kb.y, s2);
            s3 = fmaf(q[j*16 + 6], kb.z, s3); s3 = fmaf(q[j*16 + 7], kb.w, s3);
            s0 = fmaf(q[j*16 + 8], kc.x, s0); s0 = fmaf(q[j*16 + 9], kc.y, s0);
            s1 = fmaf(q[j*16 +10], kc.z, s1); s1 = fmaf(q[j*16 +11], kc.w, s1);
            s2 = fmaf(q[j*16 +12], kd.x, s2); s2 = fmaf(q[j*16 +13], kd.y, s2);
            s3 = fmaf(q[j*16 +14], kd.z, s3); s3 = fmaf(q[j*16 +15], kd.w, s3);
        }
        float s = (s0 + s1) + (s2 + s3);
        int i2 = m >> 3, j2 = m & 7;
        s += sb[(i1 - i2 + 7) * 15 + (j1 - j2 + 7)];
        if (idm_s[m] != idn) s -= 100.0f;
        float p = __expf(s);
        sum += p;
        #pragma unroll
        for (int j = 0; j < 8; j++) {
            float4 vv = vs4[m][j];
            o[j * 4 + 0] = fmaf(p, vv.x, o[j * 4 + 0]);
            o[j * 4 + 1] = fmaf(p, vv.y, o[j * 4 + 1]);
            o[j * 4 + 2] = fmaf(p, vv.z, o[j * 4 + 2]);
            o[j * 4 + 3] = fmaf(p, vv.w, o[j * 4 + 3]);
        }
    }
    float inv = 1.0f / sum;

    bf16* outp = g_attnh + (size_t)(widx * 64 + n) * 256 + h * 32;
    #pragma unroll
    for (int j = 0; j < 4; j++) {
        uint4 u;
        u.x = packbf(o[j*8+0]*inv, o[j*8+1]*inv);
        u.y = packbf(o[j*8+2]*inv, o[j*8+3]*inv);
        u.z = packbf(o[j*8+4]*inv, o[j*8+5]*inv);
        u.w = packbf(o[j*8+6]*inv, o[j*8+7]*inv);
        *(uint4*)(outp + j * 8) = u;
    }
}

// ---------------------------------------------------------------------------
// wmma bf16 GEMM: CTA 128x128, 4 warps (warp tile 64x64, 4x4 frags),
// BK=32, 4-stage cp.async pipeline, all-fragments-then-all-mma scheduling,
// fused epilogue via smem roundtrip.
// MODE 0: g_qkvh     = bf16(A @ W + b)            N=768  K=256
// MODE 1: g_x1[perm] = x[perm] + gm*(A @ W + b)   N=256  K=256
// MODE 2: g_mlph     = bf16(gelu(A @ W + b))      N=1024 K=256
// MODE 3: out        = g_x1 + gp*(A @ W + b)      N=256  K=1024
// ---------------------------------------------------------------------------
#define AS_STR 40
#define BS_STR 136
#define STAGE_B (128 * AS_STR * 2 + 32 * BS_STR * 2)   // 18944
#define GEMM_SMEM (4 * STAGE_B)                         // 75776

template <int MODE>
__global__ __launch_bounds__(128, 2)
void gemm_bf16(const float* __restrict__ bias,
               const float* __restrict__ xres,
               float* __restrict__ outp) {
    constexpr int K = (MODE == 3) ? 1024 : 256;
    constexpr int N = (MODE == 0) ? 768 : (MODE == 2) ? 1024 : 256;
    constexpr int NIT = K / 32;
    const bf16* A = (MODE == 0) ? g_hwinh : (MODE == 1) ? g_attnh
                  : (MODE == 2) ? g_h2h   : g_mlph;
    const bf16* W = g_wb + ((MODE == 0) ? WOFF_QKV : (MODE == 1) ? WOFF_PROJ
                         : (MODE == 2) ? WOFF_FC1 : WOFF_FC2);

    extern __shared__ char dsm[];
    int tid = threadIdx.x;
    int wid = tid >> 5;
    int wm = wid & 1;
    int wn = wid >> 1;
    int bm = blockIdx.y * 128, bn = blockIdx.x * 128;

    wmma::fragment<wmma::accumulator, 16, 16, 16, float> acc[4][4];
    #pragma unroll
    for (int mf = 0; mf < 4; mf++)
        #pragma unroll
        for (int nf = 0; nf < 4; nf++)
            wmma::fill_fragment(acc[mf][nf], 0.0f);

    const bf16* Abase = A + (size_t)bm * K;

    auto issue = [&](int it) {
        int buf = it & 3;
        bf16* As = (bf16*)(dsm + buf * STAGE_B);
        bf16* Bs = (bf16*)(dsm + buf * STAGE_B + 128 * AS_STR * 2);
        int k0 = it * 32;
        #pragma unroll
        for (int t = 0; t < 4; t++) {
            int idx = tid + t * 128;
            int r = idx >> 2, c = (idx & 3) * 8;
            __pipeline_memcpy_async(As + r * AS_STR + c,
                                    Abase + (size_t)r * K + k0 + c, 16);
        }
        #pragma unroll
        for (int t = 0; t < 4; t++) {
            int idx = tid + t * 128;
            int r = idx >> 4, c = (idx & 15) * 8;
            __pipeline_memcpy_async(Bs + r * BS_STR + c,
                                    W + (size_t)(k0 + r) * N + bn + c, 16);
        }
        __pipeline_commit();
    };

    issue(0);
    if (NIT > 1) issue(1);
    if (NIT > 2) issue(2);

    for (int it = 0; it < NIT; it++) {
        if (NIT - 1 - it >= 2)      __pipeline_wait_prior(2);
        else if (NIT - 1 - it == 1) __pipeline_wait_prior(1);
        else                        __pipeline_wait_prior(0);
        __syncthreads();

        const bf16* As = (const bf16*)(dsm + (it & 3) * STAGE_B);
        const bf16* Bs = (const bf16*)(dsm + (it & 3) * STAGE_B + 128 * AS_STR * 2);

        // load ALL fragments for both k-halves first, then all mma
        wmma::fragment<wmma::matrix_a, 16, 16, 16, bf16, wmma::row_major> af[2][4];
        wmma::fragment<wmma::matrix_b, 16, 16, 16, bf16, wmma::row_major> bf[2][4];
        #pragma unroll
        for (int hh = 0; hh < 2; hh++) {
            int kk = hh * 16;
            #pragma unroll
            for (int mf = 0; mf < 4; mf++)
                wmma::load_matrix_sync(af[hh][mf], As + (wm * 64 + mf * 16) * AS_STR + kk, AS_STR);
            #pragma unroll
            for (int nf = 0; nf < 4; nf++)
                wmma::load_matrix_sync(bf[hh][nf], Bs + kk * BS_STR + wn * 64 + nf * 16, BS_STR);
        }
        #pragma unroll
        for (int hh = 0; hh < 2; hh++)
            #pragma unroll
            for (int mf = 0; mf < 4; mf++)
                #pragma unroll
                for (int nf = 0; nf < 4; nf++)
                    wmma::mma_sync(acc[mf][nf], af[hh][mf], bf[hh][nf], acc[mf][nf]);

        if (it + 3 < NIT) issue(it + 3);
    }
    __syncthreads();

    // ---- epilogue via smem roundtrip (alias stage buffers: 64KB fp32) ----
    float* epi = (float*)dsm;
    #pragma unroll
    for (int mf = 0; mf < 4; mf++)
        #pragma unroll
        for (int nf = 0; nf < 4; nf++)
            wmma::store_matrix_sync(epi + (wm * 64 + mf * 16) * 128 + wn * 64 + nf * 16,
                                    acc[mf][nf], 128, wmma::mem_row_major);
    __syncthreads();

    #pragma unroll
    for (int t = 0; t < 16; t++) {
        int ch = tid + t * 128;
        int r = ch >> 4;
        int c8 = (ch & 15) * 8;
        int col = bn + c8;
        int row = bm + r;
        float v[8];
        *(float4*)(v)     = *(const float4*)(epi + r * 128 + c8);
        *(float4*)(v + 4) = *(const float4*)(epi + r * 128 + c8 + 4);
        #pragma unroll
        for (int j = 0; j < 8; j++) v[j] += __ldg(&bias[col + j]);

        if (MODE == 0) {
            uint4 u;
            u.x = packbf(v[0], v[1]); u.y = packbf(v[2], v[3]);
            u.z = packbf(v[4], v[5]); u.w = packbf(v[6], v[7]);
            *(uint4*)(g_qkvh + (size_t)row * 768 + col) = u;
        } else if (MODE == 1) {
            int b = row >> 12, tt = row & 63, widx = (row >> 6) & 63;
            int wh = (widx >> 3) & 7, ww = widx & 7;
            int pr = (wh * 8 + (tt >> 3) + 4) & 63;
            int pc = (ww * 8 + (tt & 7) + 4) & 63;
            size_t prow = (size_t)(b * 4096 + pr * 64 + pc);
            const float* gm = g_ada + b * 1536 + 512;
            float o[8];
            #pragma unroll
            for (int j = 0; j < 8; j++)
                o[j] = __ldg(&xres[prow * 256 + col + j]) + gm[col + j] * v[j];
            *(float4*)(g_x1 + prow * 256 + col)     = *(float4*)(o);
            *(float4*)(g_x1 + prow * 256 + col + 4) = *(float4*)(o + 4);
        } else if (MODE == 2) {
            uint4 u;
            float o[8];
            #pragma unroll
            for (int j = 0; j < 8; j++)
                o[j] = 0.5f * v[j] * (1.0f + erff(v[j] * 0.70710678118654752f));
            u.x = packbf(o[0], o[1]); u.y = packbf(o[2], o[3]);
            u.z = packbf(o[4], o[5]); u.w = packbf(o[6], o[7]);
            *(uint4*)(g_mlph + (size_t)row * 1024 + col) = u;
        } else {
            int b = row >> 12;
            const float* gp = g_ada + b * 1536 + 1280;
            const float* x1 = g_x1 + (size_t)row * 256 + col;
            float o[8];
            #pragma unroll
            for (int j = 0; j < 8; j++)
                o[j] = x1[j] + gp[col + j] * v[j];
            *(float4*)(outp + (size_t)row * 256 + col)     = *(float4*)(o);
            *(float4*)(outp + (size_t)row * 256 + col + 4) = *(float4*)(o + 4);
        }
    }
}

// ---------------------------------------------------------------------------
extern "C" void kernel_launch(void* const* d_in, const int* in_sizes, int n_in,
                              void* d_out, int out_size) {
    const float* x       = (const float*)d_in[0];
    const float* cond    = (const float*)d_in[1];
    const float* norm1_g = (const float*)d_in[2];
    const float* norm1_b = (const float*)d_in[3];
    const float* w_qkv   = (const float*)d_in[4];
    const float* b_qkv   = (const float*)d_in[5];
    const float* rel_b   = (const float*)d_in[6];
    const float* w_proj  = (const float*)d_in[7];
    const float* b_proj  = (const float*)d_in[8];
    const float* norm2_g = (const float*)d_in[9];
    const float* norm2_b = (const float*)d_in[10];
    const float* w_fc1   = (const float*)d_in[11];
    const float* b_fc1   = (const float*)d_in[12];
    const float* w_fc2   = (const float*)d_in[13];
    const float* b_fc2   = (const float*)d_in[14];
    const float* w_ada   = (const float*)d_in[15];
    const float* b_ada   = (const float*)d_in[16];
    float* out = (float*)d_out;

    cudaFuncSetAttribute(gemm_bf16<0>, cudaFuncAttributeMaxDynamicSharedMemorySize, GEMM_SMEM);
    cudaFuncSetAttribute(gemm_bf16<1>, cudaFuncAttributeMaxDynamicSharedMemorySize, GEMM_SMEM);
    cudaFuncSetAttribute(gemm_bf16<2>, cudaFuncAttributeMaxDynamicSharedMemorySize, GEMM_SMEM);
    cudaFuncSetAttribute(gemm_bf16<3>, cudaFuncAttributeMaxDynamicSharedMemorySize, GEMM_SMEM);

    cvt_all_kernel<<<768, 256>>>(w_qkv, w_proj, w_fc1, w_fc2);
    ada_kernel<<<16, 256>>>(cond, w_ada, b_ada);
    ln_mod_kernel<0><<<8192, 256>>>(x, norm1_g, norm1_b);
    gemm_bf16<0><<<dim3(6, 512), 128, GEMM_SMEM>>>(b_qkv, nullptr, nullptr);
    attn_kernel<<<dim3(1024, 8), 64>>>(rel_b);
    gemm_bf16<1><<<dim3(2, 512), 128, GEMM_SMEM>>>(b_proj, x, nullptr);
    ln_mod_kernel<1><<<8192, 256>>>(nullptr, norm2_g, norm2_b);
    gemm_bf16<2><<<dim3(8, 512), 128, GEMM_SMEM>>>(b_fc1, nullptr, nullptr);
    gemm_bf16<3><<<dim3(2, 512), 128, GEMM_SMEM>>>(b_fc2, nullptr, out);
}

// round 14
// speedup vs baseline: 1.0807x; 1.0746x over previous
#include <cuda_runtime.h>
#include <cuda_bf16.h>
#include <cuda_pipeline_primitives.h>
#include <mma.h>
#include <math.h>

using namespace nvcuda;

// ---------------------------------------------------------------------------
// WITT AdaLN Swin block. wmma bf16 GEMMs + wmma attention.
// B=16, H=W=64, C=256, NH=8, HD=32, WS=8, SS=4, N=64, NWIN=64, MLP_H=1024.
// ---------------------------------------------------------------------------

#define TOK 65536
typedef __nv_bfloat16 bf16;

__device__ __align__(16) float g_ada  [16 * 1536];
__device__ __align__(16) bf16  g_wb   [786432];             // bf16 weights [K,N]
__device__ __align__(16) bf16  g_hwinh[(size_t)TOK * 256];
__device__ __align__(16) bf16  g_qkvh [(size_t)TOK * 768];
__device__ __align__(16) bf16  g_attnh[(size_t)TOK * 256];
__device__ __align__(16) float g_x1   [(size_t)TOK * 256];
__device__ __align__(16) bf16  g_h2h  [(size_t)TOK * 256];
__device__ __align__(16) bf16  g_mlph [(size_t)TOK * 1024];

#define WOFF_QKV  0
#define WOFF_PROJ 196608
#define WOFF_FC1  262144
#define WOFF_FC2  524288

__device__ __forceinline__ uint32_t packbf(float a, float b) {
    __nv_bfloat162 t = __floats2bfloat162_rn(a, b);
    return *reinterpret_cast<uint32_t*>(&t);
}

// ---------------------------------------------------------------------------
// all-weights fp32 -> bf16 (single launch). 196608 chunks of 4 floats.
// ---------------------------------------------------------------------------
__global__ void cvt_all_kernel(const float* __restrict__ w_qkv,
                               const float* __restrict__ w_proj,
                               const float* __restrict__ w_fc1,
                               const float* __restrict__ w_fc2) {
    int i = blockIdx.x * blockDim.x + threadIdx.x;
    const float* src; int off;
    if (i < 49152)       { src = w_qkv;  off = 0; }
    else if (i < 65536)  { src = w_proj; off = 49152; }
    else if (i < 131072) { src = w_fc1;  off = 65536; }
    else                 { src = w_fc2;  off = 131072; }
    float4 v = __ldg((const float4*)src + (i - off));
    uint2 u;
    u.x = packbf(v.x, v.y);
    u.y = packbf(v.z, v.w);
    *((uint2*)g_wb + i) = u;
}

// ---------------------------------------------------------------------------
// ada = silu(cond) @ w_ada + b_ada   [16,1536]
// ---------------------------------------------------------------------------
__global__ void ada_kernel(const float* __restrict__ cond,
                           const float* __restrict__ w_ada,
                           const float* __restrict__ b_ada) {
    __shared__ float sc[256];
    int b = blockIdx.x, t = threadIdx.x;
    float v = cond[b * 256 + t];
    sc[t] = v / (1.0f + expf(-v));
    __syncthreads();
    for (int j = t; j < 1536; j += 256) {
        float acc = b_ada[j];
        #pragma unroll 4
        for (int i = 0; i < 256; i++) acc = fmaf(sc[i], __ldg(&w_ada[i * 1536 + j]), acc);
        g_ada[b * 1536 + j] = acc;
    }
}

// ---------------------------------------------------------------------------
// LN + AdaLN -> bf16. PASS 0: roll(-4,-4)+window partition; PASS 1: plain.
// ---------------------------------------------------------------------------
template <int PASS>
__global__ void ln_mod_kernel(const float* __restrict__ xin,
                              const float* __restrict__ gamma,
                              const float* __restrict__ beta) {
    int gw   = (blockIdx.x * blockDim.x + threadIdx.x) >> 5;
    int lane = threadIdx.x & 31;
    int b = gw >> 12;

    const float* src;
    bf16* dst;
    if (PASS == 0) {
        int t = gw & 63, widx = (gw >> 6) & 63;
        int wh = (widx >> 3) & 7, ww = widx & 7;
        int sr  = (wh * 8 + (t >> 3) + 4) & 63;
        int sc2 = (ww * 8 + (t & 7) + 4) & 63;
        src = xin + ((size_t)(b * 4096 + sr * 64 + sc2)) * 256;
        dst = g_hwinh + (size_t)gw * 256;
    } else {
        src = g_x1 + (size_t)gw * 256;
        dst = g_h2h + (size_t)gw * 256;
    }

    float4 v0 = *(const float4*)(src + lane * 8);
    float4 v1 = *(const float4*)(src + lane * 8 + 4);
    float e[8] = {v0.x, v0.y, v0.z, v0.w, v1.x, v1.y, v1.z, v1.w};

    float s = 0.f, q = 0.f;
    #pragma unroll
    for (int j = 0; j < 8; j++) { s += e[j]; q += e[j] * e[j]; }
    #pragma unroll
    for (int off = 16; off > 0; off >>= 1) {
        s += __shfl_xor_sync(0xffffffffu, s, off);
        q += __shfl_xor_sync(0xffffffffu, q, off);
    }
    float mean = s * (1.0f / 256.0f);
    float var  = q * (1.0f / 256.0f) - mean * mean;
    float rstd = rsqrtf(var + 1e-5f);

    const float* scl = g_ada + b * 1536 + (PASS == 0 ? 256 : 1024);
    const float* sft = g_ada + b * 1536 + (PASS == 0 ? 0   : 768);

    int ch = lane * 8;
    float o[8];
    #pragma unroll
    for (int j = 0; j < 8; j++) {
        float y = (e[j] - mean) * rstd * __ldg(&gamma[ch + j]) + __ldg(&beta[ch + j]);
        o[j] = y * (1.0f + scl[ch + j]) + sft[ch + j];
    }
    uint4 u;
    u.x = packbf(o[0], o[1]); u.y = packbf(o[2], o[3]);
    u.z = packbf(o[4], o[5]); u.w = packbf(o[6], o[7]);
    *(uint4*)(dst + ch) = u;
}

// ---------------------------------------------------------------------------
// wmma attention: one block = one (window, head). 128 threads / 4 warps.
// S = Q K^T (wmma, col_major K trick); softmax with fused scale+bias+mask;
// O = P V (wmma, bf16 P); normalize by row-sum in epilogue.
// ---------------------------------------------------------------------------
__global__ __launch_bounds__(128)
void attn_wmma_kernel(const float* __restrict__ rel_bias) {
    __shared__ bf16  Qs[64][40];
    __shared__ bf16  Ks[64][40];
    __shared__ bf16  Vs[64][40];
    __shared__ float Ss[64][72];          // also aliased as Os (ldm 36) after softmax
    __shared__ bf16  Ps[64][72];
    __shared__ float sb[225];
    __shared__ int   idm[64];
    __shared__ float rinv[64];

    int widx = blockIdx.x;
    int h    = blockIdx.y;
    int tid  = threadIdx.x;
    int w    = tid >> 5;

    for (int i = tid; i < 225; i += 128) sb[i] = __ldg(&rel_bias[i * 8 + h]);
    if (tid < 64) {
        int wh = (widx >> 3) & 7, ww = widx & 7;
        int rv = wh * 8 + (tid >> 3), cv = ww * 8 + (tid & 7);
        idm[tid] = (rv < 56 ? 0 : (rv < 60 ? 1 : 2)) * 3 +
                   (cv < 56 ? 0 : (cv < 60 ? 1 : 2));
    }

    // copy Q/K/V rows (pure uint4 copies; data already bf16)
    {
        int n = tid >> 1, hf = tid & 1;
        const bf16* rowp = g_qkvh + (size_t)widx * 64 * 768 + (size_t)n * 768 + h * 32;
        #pragma unroll
        for (int j = 0; j < 2; j++) {
            int c = hf * 16 + j * 8;
            *(uint4*)&Qs[n][c] = *(const uint4*)(rowp + c);
            *(uint4*)&Ks[n][c] = *(const uint4*)(rowp + 256 + c);
            *(uint4*)&Vs[n][c] = *(const uint4*)(rowp + 512 + c);
        }
    }
    __syncthreads();

    // ---- S = Q K^T ----
    {
        wmma::fragment<wmma::matrix_a, 16, 16, 16, bf16, wmma::row_major> a[2];
        wmma::fragment<wmma::matrix_b, 16, 16, 16, bf16, wmma::col_major> b;
        wmma::fragment<wmma::accumulator, 16, 16, 16, float> acc[4];
        #pragma unroll
        for (int nf = 0; nf < 4; nf++) wmma::fill_fragment(acc[nf], 0.0f);
        #pragma unroll
        for (int kf = 0; kf < 2; kf++)
            wmma::load_matrix_sync(a[kf], &Qs[w * 16][kf * 16], 40);
        #pragma unroll
        for (int kf = 0; kf < 2; kf++)
            #pragma unroll
            for (int nf = 0; nf < 4; nf++) {
                wmma::load_matrix_sync(b, &Ks[nf * 16][kf * 16], 40);
                wmma::mma_sync(acc[nf], a[kf], b, acc[nf]);
            }
        #pragma unroll
        for (int nf = 0; nf < 4; nf++)
            wmma::store_matrix_sync(&Ss[w * 16][nf * 16], acc[nf], 72, wmma::mem_row_major);
    }
    __syncthreads();

    // ---- softmax (unnormalized; scale fused) ----
    int r = tid >> 1, hf = tid & 1;
    {
        const float scale = 0.17677669529663687f;
        int i1 = r >> 3, j1 = r & 7;
        int my = idm[r];
        float sum = 0.f;
        #pragma unroll
        for (int c = 0; c < 32; c++) {
            int m = hf * 32 + c;
            float s = fmaf(Ss[r][m], scale,
                           sb[(i1 - (m >> 3) + 7) * 15 + (j1 - (m & 7) + 7)]);
            if (idm[m] != my) s -= 100.0f;
            float p = __expf(s);
            sum += p;
            Ps[r][m] = __float2bfloat16(p);
        }
        sum += __shfl_xor_sync(0xffffffffu, sum, 1);
        if (hf == 0) rinv[r] = 1.0f / sum;
    }
    __syncthreads();

    // ---- O = P V ----  (Os aliases Ss, ldm 36)
    float* Os = &Ss[0][0];
    {
        wmma::fragment<wmma::matrix_a, 16, 16, 16, bf16, wmma::row_major> pa;
        wmma::fragment<wmma::matrix_b, 16, 16, 16, bf16, wmma::row_major> vb;
        wmma::fragment<wmma::accumulator, 16, 16, 16, float> oacc[2];
        #pragma unroll
        for (int nf = 0; nf < 2; nf++) wmma::fill_fragment(oacc[nf], 0.0f);
        #pragma unroll
        for (int kf = 0; kf < 4; kf++) {
            wmma::load_matrix_sync(pa, &Ps[w * 16][kf * 16], 72);
            #pragma unroll
            for (int nf = 0; nf < 2; nf++) {
                wmma::load_matrix_sync(vb, &Vs[kf * 16][nf * 16], 40);
                wmma::mma_sync(oacc[nf], pa, vb, oacc[nf]);
            }
        }
        #pragma unroll
        for (int nf = 0; nf < 2; nf++)
            wmma::store_matrix_sync(Os + (w * 16) * 36 + nf * 16, oacc[nf], 36,
                                    wmma::mem_row_major);
    }
    __syncthreads();

    // ---- epilogue: normalize + write bf16 ----
    {
        float inv = rinv[r];
        const float* orow = Os + r * 36 + hf * 16;
        bf16* outp = g_attnh + (size_t)(widx * 64 + r) * 256 + h * 32 + hf * 16;
        float o[16];
        *(float4*)(o)      = *(const float4*)(orow);
        *(float4*)(o + 4)  = *(const float4*)(orow + 4);
        *(float4*)(o + 8)  = *(const float4*)(orow + 8);
        *(float4*)(o + 12) = *(const float4*)(orow + 12);
        uint4 u0, u1;
        u0.x = packbf(o[0] * inv,  o[1] * inv);
        u0.y = packbf(o[2] * inv,  o[3] * inv);
        u0.z = packbf(o[4] * inv,  o[5] * inv);
        u0.w = packbf(o[6] * inv,  o[7] * inv);
        u1.x = packbf(o[8] * inv,  o[9] * inv);
        u1.y = packbf(o[10] * inv, o[11] * inv);
        u1.z = packbf(o[12] * inv, o[13] * inv);
        u1.w = packbf(o[14] * inv, o[15] * inv);
        *(uint4*)(outp)     = u0;
        *(uint4*)(outp + 8) = u1;
    }
}

// ---------------------------------------------------------------------------
// wmma bf16 GEMM: CTA 128x128, 4 warps (warp tile 64x64, 4x4 frags),
// BK=32, 4-stage cp.async pipeline, fused epilogue via smem roundtrip.
// MODE 0: g_qkvh     = bf16(A @ W + b)            N=768  K=256
// MODE 1: g_x1[perm] = x[perm] + gm*(A @ W + b)   N=256  K=256
// MODE 2: g_mlph     = bf16(gelu(A @ W + b))      N=1024 K=256
// MODE 3: out        = g_x1 + gp*(A @ W + b)      N=256  K=1024
// ---------------------------------------------------------------------------
#define AS_STR 40
#define BS_STR 136
#define STAGE_B (128 * AS_STR * 2 + 32 * BS_STR * 2)   // 18944
#define GEMM_SMEM (4 * STAGE_B)                         // 75776

template <int MODE>
__global__ __launch_bounds__(128, 2)
void gemm_bf16(const float* __restrict__ bias,
               const float* __restrict__ xres,
               float* __restrict__ outp) {
    constexpr int K = (MODE == 3) ? 1024 : 256;
    constexpr int N = (MODE == 0) ? 768 : (MODE == 2) ? 1024 : 256;
    constexpr int NIT = K / 32;
    const bf16* A = (MODE == 0) ? g_hwinh : (MODE == 1) ? g_attnh
                  : (MODE == 2) ? g_h2h   : g_mlph;
    const bf16* W = g_wb + ((MODE == 0) ? WOFF_QKV : (MODE == 1) ? WOFF_PROJ
                         : (MODE == 2) ? WOFF_FC1 : WOFF_FC2);

    extern __shared__ char dsm[];
    int tid = threadIdx.x;
    int wid = tid >> 5;
    int wm = wid & 1;
    int wn = wid >> 1;
    int bm = blockIdx.y * 128, bn = blockIdx.x * 128;

    wmma::fragment<wmma::accumulator, 16, 16, 16, float> acc[4][4];
    #pragma unroll
    for (int mf = 0; mf < 4; mf++)
        #pragma unroll
        for (int nf = 0; nf < 4; nf++)
            wmma::fill_fragment(acc[mf][nf], 0.0f);

    const bf16* Abase = A + (size_t)bm * K;

    auto issue = [&](int it) {
        int buf = it & 3;
        bf16* As = (bf16*)(dsm + buf * STAGE_B);
        bf16* Bs = (bf16*)(dsm + buf * STAGE_B + 128 * AS_STR * 2);
        int k0 = it * 32;
        #pragma unroll
        for (int t = 0; t < 4; t++) {
            int idx = tid + t * 128;
            int r = idx >> 2, c = (idx & 3) * 8;
            __pipeline_memcpy_async(As + r * AS_STR + c,
                                    Abase + (size_t)r * K + k0 + c, 16);
        }
        #pragma unroll
        for (int t = 0; t < 4; t++) {
            int idx = tid + t * 128;
            int r = idx >> 4, c = (idx & 15) * 8;
            __pipeline_memcpy_async(Bs + r * BS_STR + c,
                                    W + (size_t)(k0 + r) * N + bn + c, 16);
        }
        __pipeline_commit();
    };

    issue(0);
    if (NIT > 1) issue(1);
    if (NIT > 2) issue(2);

    for (int it = 0; it < NIT; it++) {
        if (NIT - 1 - it >= 2)      __pipeline_wait_prior(2);
        else if (NIT - 1 - it == 1) __pipeline_wait_prior(1);
        else                        __pipeline_wait_prior(0);
        __syncthreads();

        const bf16* As = (const bf16*)(dsm + (it & 3) * STAGE_B);
        const bf16* Bs = (const bf16*)(dsm + (it & 3) * STAGE_B + 128 * AS_STR * 2);
        #pragma unroll
        for (int kk = 0; kk < 32; kk += 16) {
            wmma::fragment<wmma::matrix_a, 16, 16, 16, bf16, wmma::row_major> af[4];
            wmma::fragment<wmma::matrix_b, 16, 16, 16, bf16, wmma::row_major> bf[4];
            #pragma unroll
            for (int mf = 0; mf < 4; mf++)
                wmma::load_matrix_sync(af[mf], As + (wm * 64 + mf * 16) * AS_STR + kk, AS_STR);
            #pragma unroll
            for (int nf = 0; nf < 4; nf++)
                wmma::load_matrix_sync(bf[nf], Bs + kk * BS_STR + wn * 64 + nf * 16, BS_STR);
            #pragma unroll
            for (int mf = 0; mf < 4; mf++)
                #pragma unroll
                for (int nf = 0; nf < 4; nf++)
                    wmma::mma_sync(acc[mf][nf], af[mf], bf[nf], acc[mf][nf]);
        }
        if (it + 3 < NIT) issue(it + 3);
    }
    __syncthreads();

    // ---- epilogue via smem roundtrip (alias stage buffers: 64KB fp32) ----
    float* epi = (float*)dsm;
    #pragma unroll
    for (int mf = 0; mf < 4; mf++)
        #pragma unroll
        for (int nf = 0; nf < 4; nf++)
            wmma::store_matrix_sync(epi + (wm * 64 + mf * 16) * 128 + wn * 64 + nf * 16,
                                    acc[mf][nf], 128, wmma::mem_row_major);
    __syncthreads();

    #pragma unroll
    for (int t = 0; t < 16; t++) {
        int ch = tid + t * 128;
        int r = ch >> 4;
        int c8 = (ch & 15) * 8;
        int col = bn + c8;
        int row = bm + r;
        float v[8];
        *(float4*)(v)     = *(const float4*)(epi + r * 128 + c8);
        *(float4*)(v + 4) = *(const float4*)(epi + r * 128 + c8 + 4);
        #pragma unroll
        for (int j = 0; j < 8; j++) v[j] += __ldg(&bias[col + j]);

        if (MODE == 0) {
            uint4 u;
            u.x = packbf(v[0], v[1]); u.y = packbf(v[2], v[3]);
            u.z = packbf(v[4], v[5]); u.w = packbf(v[6], v[7]);
            *(uint4*)(g_qkvh + (size_t)row * 768 + col) = u;
        } else if (MODE == 1) {
            int b = row >> 12, tt = row & 63, widx = (row >> 6) & 63;
            int wh = (widx >> 3) & 7, ww = widx & 7;
            int pr = (wh * 8 + (tt >> 3) + 4) & 63;
            int pc = (ww * 8 + (tt & 7) + 4) & 63;
            size_t prow = (size_t)(b * 4096 + pr * 64 + pc);
            const float* gm = g_ada + b * 1536 + 512;
            float o[8];
            #pragma unroll
            for (int j = 0; j < 8; j++)
                o[j] = __ldg(&xres[prow * 256 + col + j]) + gm[col + j] * v[j];
            *(float4*)(g_x1 + prow * 256 + col)     = *(float4*)(o);
            *(float4*)(g_x1 + prow * 256 + col + 4) = *(float4*)(o + 4);
        } else if (MODE == 2) {
            uint4 u;
            float o[8];
            #pragma unroll
            for (int j = 0; j < 8; j++)
                o[j] = 0.5f * v[j] * (1.0f + erff(v[j] * 0.70710678118654752f));
            u.x = packbf(o[0], o[1]); u.y = packbf(o[2], o[3]);
            u.z = packbf(o[4], o[5]); u.w = packbf(o[6], o[7]);
            *(uint4*)(g_mlph + (size_t)row * 1024 + col) = u;
        } else {
            int b = row >> 12;
            const float* gp = g_ada + b * 1536 + 1280;
            const float* x1 = g_x1 + (size_t)row * 256 + col;
            float o[8];
            #pragma unroll
            for (int j = 0; j < 8; j++)
                o[j] = x1[j] + gp[col + j] * v[j];
            *(float4*)(outp + (size_t)row * 256 + col)     = *(float4*)(o);
            *(float4*)(outp + (size_t)row * 256 + col + 4) = *(float4*)(o + 4);
        }
    }
}

// ---------------------------------------------------------------------------
extern "C" void kernel_launch(void* const* d_in, const int* in_sizes, int n_in,
                              void* d_out, int out_size) {
    const float* x       = (const float*)d_in[0];
    const float* cond    = (const float*)d_in[1];
    const float* norm1_g = (const float*)d_in[2];
    const float* norm1_b = (const float*)d_in[3];
    const float* w_qkv   = (const float*)d_in[4];
    const float* b_qkv   = (const float*)d_in[5];
    const float* rel_b   = (const float*)d_in[6];
    const float* w_proj  = (const float*)d_in[7];
    const float* b_proj  = (const float*)d_in[8];
    const float* norm2_g = (const float*)d_in[9];
    const float* norm2_b = (const float*)d_in[10];
    const float* w_fc1   = (const float*)d_in[11];
    const float* b_fc1   = (const float*)d_in[12];
    const float* w_fc2   = (const float*)d_in[13];
    const float* b_fc2   = (const float*)d_in[14];
    const float* w_ada   = (const float*)d_in[15];
    const float* b_ada   = (const float*)d_in[16];
    float* out = (float*)d_out;

    cudaFuncSetAttribute(gemm_bf16<0>, cudaFuncAttributeMaxDynamicSharedMemorySize, GEMM_SMEM);
    cudaFuncSetAttribute(gemm_bf16<1>, cudaFuncAttributeMaxDynamicSharedMemorySize, GEMM_SMEM);
    cudaFuncSetAttribute(gemm_bf16<2>, cudaFuncAttributeMaxDynamicSharedMemorySize, GEMM_SMEM);
    cudaFuncSetAttribute(gemm_bf16<3>, cudaFuncAttributeMaxDynamicSharedMemorySize, GEMM_SMEM);

    cvt_all_kernel<<<768, 256>>>(w_qkv, w_proj, w_fc1, w_fc2);
    ada_kernel<<<16, 256>>>(cond, w_ada, b_ada);
    ln_mod_kernel<0><<<8192, 256>>>(x, norm1_g, norm1_b);
    gemm_bf16<0><<<dim3(6, 512), 128, GEMM_SMEM>>>(b_qkv, nullptr, nullptr);
    attn_wmma_kernel<<<dim3(1024, 8), 128>>>(rel_b);
    gemm_bf16<1><<<dim3(2, 512), 128, GEMM_SMEM>>>(b_proj, x, nullptr);
    ln_mod_kernel<1><<<8192, 256>>>(nullptr, norm2_g, norm2_b);
    gemm_bf16<2><<<dim3(8, 512), 128, GEMM_SMEM>>>(b_fc1, nullptr, nullptr);
    gemm_bf16<3><<<dim3(2, 512), 128, GEMM_SMEM>>>(b_fc2, nullptr, out);
}

// round 15
// speedup vs baseline: 1.1128x; 1.0296x over previous
#include <cuda_runtime.h>
#include <cuda_bf16.h>
#include <cuda_pipeline_primitives.h>
#include <mma.h>
#include <math.h>

using namespace nvcuda;

// ---------------------------------------------------------------------------
// WITT AdaLN Swin block. wmma bf16 GEMMs (3-stage pipeline) + wmma attention.
// B=16, H=W=64, C=256, NH=8, HD=32, WS=8, SS=4, N=64, NWIN=64, MLP_H=1024.
// ---------------------------------------------------------------------------

#define TOK 65536
typedef __nv_bfloat16 bf16;

__device__ __align__(16) float g_ada  [16 * 1536];
__device__ __align__(16) bf16  g_wb   [786432];             // bf16 weights [K,N]
__device__ __align__(16) bf16  g_hwinh[(size_t)TOK * 256];
__device__ __align__(16) bf16  g_qkvh [(size_t)TOK * 768];
__device__ __align__(16) bf16  g_attnh[(size_t)TOK * 256];
__device__ __align__(16) float g_x1   [(size_t)TOK * 256];
__device__ __align__(16) bf16  g_h2h  [(size_t)TOK * 256];
__device__ __align__(16) bf16  g_mlph [(size_t)TOK * 1024];

#define WOFF_QKV  0
#define WOFF_PROJ 196608
#define WOFF_FC1  262144
#define WOFF_FC2  524288

__device__ __forceinline__ uint32_t packbf(float a, float b) {
    __nv_bfloat162 t = __floats2bfloat162_rn(a, b);
    return *reinterpret_cast<uint32_t*>(&t);
}

// ---------------------------------------------------------------------------
// all-weights fp32 -> bf16 (single launch). 196608 chunks of 4 floats.
// ---------------------------------------------------------------------------
__global__ void cvt_all_kernel(const float* __restrict__ w_qkv,
                               const float* __restrict__ w_proj,
                               const float* __restrict__ w_fc1,
                               const float* __restrict__ w_fc2) {
    int i = blockIdx.x * blockDim.x + threadIdx.x;
    const float* src; int off;
    if (i < 49152)       { src = w_qkv;  off = 0; }
    else if (i < 65536)  { src = w_proj; off = 49152; }
    else if (i < 131072) { src = w_fc1;  off = 65536; }
    else                 { src = w_fc2;  off = 131072; }
    float4 v = __ldg((const float4*)src + (i - off));
    uint2 u;
    u.x = packbf(v.x, v.y);
    u.y = packbf(v.z, v.w);
    *((uint2*)g_wb + i) = u;
}

// ---------------------------------------------------------------------------
// ada = silu(cond) @ w_ada + b_ada   [16,1536]
// ---------------------------------------------------------------------------
__global__ void ada_kernel(const float* __restrict__ cond,
                           const float* __restrict__ w_ada,
                           const float* __restrict__ b_ada) {
    __shared__ float sc[256];
    int b = blockIdx.x, t = threadIdx.x;
    float v = cond[b * 256 + t];
    sc[t] = v / (1.0f + expf(-v));
    __syncthreads();
    for (int j = t; j < 1536; j += 256) {
        float acc = b_ada[j];
        #pragma unroll 4
        for (int i = 0; i < 256; i++) acc = fmaf(sc[i], __ldg(&w_ada[i * 1536 + j]), acc);
        g_ada[b * 1536 + j] = acc;
    }
}

// ---------------------------------------------------------------------------
// LN + AdaLN -> bf16. PASS 0: roll(-4,-4)+window partition; PASS 1: plain.
// ---------------------------------------------------------------------------
template <int PASS>
__global__ void ln_mod_kernel(const float* __restrict__ xin,
                              const float* __restrict__ gamma,
                              const float* __restrict__ beta) {
    int gw   = (blockIdx.x * blockDim.x + threadIdx.x) >> 5;
    int lane = threadIdx.x & 31;
    int b = gw >> 12;

    const float* src;
    bf16* dst;
    if (PASS == 0) {
        int t = gw & 63, widx = (gw >> 6) & 63;
        int wh = (widx >> 3) & 7, ww = widx & 7;
        int sr  = (wh * 8 + (t >> 3) + 4) & 63;
        int sc2 = (ww * 8 + (t & 7) + 4) & 63;
        src = xin + ((size_t)(b * 4096 + sr * 64 + sc2)) * 256;
        dst = g_hwinh + (size_t)gw * 256;
    } else {
        src = g_x1 + (size_t)gw * 256;
        dst = g_h2h + (size_t)gw * 256;
    }

    float4 v0 = *(const float4*)(src + lane * 8);
    float4 v1 = *(const float4*)(src + lane * 8 + 4);
    float e[8] = {v0.x, v0.y, v0.z, v0.w, v1.x, v1.y, v1.z, v1.w};

    float s = 0.f, q = 0.f;
    #pragma unroll
    for (int j = 0; j < 8; j++) { s += e[j]; q += e[j] * e[j]; }
    #pragma unroll
    for (int off = 16; off > 0; off >>= 1) {
        s += __shfl_xor_sync(0xffffffffu, s, off);
        q += __shfl_xor_sync(0xffffffffu, q, off);
    }
    float mean = s * (1.0f / 256.0f);
    float var  = q * (1.0f / 256.0f) - mean * mean;
    float rstd = rsqrtf(var + 1e-5f);

    const float* scl = g_ada + b * 1536 + (PASS == 0 ? 256 : 1024);
    const float* sft = g_ada + b * 1536 + (PASS == 0 ? 0   : 768);

    int ch = lane * 8;
    float o[8];
    #pragma unroll
    for (int j = 0; j < 8; j++) {
        float y = (e[j] - mean) * rstd * __ldg(&gamma[ch + j]) + __ldg(&beta[ch + j]);
        o[j] = y * (1.0f + scl[ch + j]) + sft[ch + j];
    }
    uint4 u;
    u.x = packbf(o[0], o[1]); u.y = packbf(o[2], o[3]);
    u.z = packbf(o[4], o[5]); u.w = packbf(o[6], o[7]);
    *(uint4*)(dst + ch) = u;
}

// ---------------------------------------------------------------------------
// wmma attention: one block = one (window, head). 128 threads / 4 warps.
// ---------------------------------------------------------------------------
__global__ __launch_bounds__(128)
void attn_wmma_kernel(const float* __restrict__ rel_bias) {
    __shared__ bf16  Qs[64][40];
    __shared__ bf16  Ks[64][40];
    __shared__ bf16  Vs[64][40];
    __shared__ float Ss[64][72];          // aliased as Os (ldm 36) after softmax
    __shared__ bf16  Ps[64][72];
    __shared__ float sb[225];
    __shared__ int   idm[64];
    __shared__ float rinv[64];

    int widx = blockIdx.x;
    int h    = blockIdx.y;
    int tid  = threadIdx.x;
    int w    = tid >> 5;

    for (int i = tid; i < 225; i += 128) sb[i] = __ldg(&rel_bias[i * 8 + h]);
    if (tid < 64) {
        int wh = (widx >> 3) & 7, ww = widx & 7;
        int rv = wh * 8 + (tid >> 3), cv = ww * 8 + (tid & 7);
        idm[tid] = (rv < 56 ? 0 : (rv < 60 ? 1 : 2)) * 3 +
                   (cv < 56 ? 0 : (cv < 60 ? 1 : 2));
    }

    {
        int n = tid >> 1, hf = tid & 1;
        const bf16* rowp = g_qkvh + (size_t)widx * 64 * 768 + (size_t)n * 768 + h * 32;
        #pragma unroll
        for (int j = 0; j < 2; j++) {
            int c = hf * 16 + j * 8;
            *(uint4*)&Qs[n][c] = *(const uint4*)(rowp + c);
            *(uint4*)&Ks[n][c] = *(const uint4*)(rowp + 256 + c);
            *(uint4*)&Vs[n][c] = *(const uint4*)(rowp + 512 + c);
        }
    }
    __syncthreads();

    // ---- S = Q K^T ----
    {
        wmma::fragment<wmma::matrix_a, 16, 16, 16, bf16, wmma::row_major> a[2];
        wmma::fragment<wmma::matrix_b, 16, 16, 16, bf16, wmma::col_major> b;
        wmma::fragment<wmma::accumulator, 16, 16, 16, float> acc[4];
        #pragma unroll
        for (int nf = 0; nf < 4; nf++) wmma::fill_fragment(acc[nf], 0.0f);
        #pragma unroll
        for (int kf = 0; kf < 2; kf++)
            wmma::load_matrix_sync(a[kf], &Qs[w * 16][kf * 16], 40);
        #pragma unroll
        for (int kf = 0; kf < 2; kf++)
            #pragma unroll
            for (int nf = 0; nf < 4; nf++) {
                wmma::load_matrix_sync(b, &Ks[nf * 16][kf * 16], 40);
                wmma::mma_sync(acc[nf], a[kf], b, acc[nf]);
            }
        #pragma unroll
        for (int nf = 0; nf < 4; nf++)
            wmma::store_matrix_sync(&Ss[w * 16][nf * 16], acc[nf], 72, wmma::mem_row_major);
    }
    __syncthreads();

    // ---- softmax (unnormalized; scale fused) ----
    int r = tid >> 1, hf = tid & 1;
    {
        const float scale = 0.17677669529663687f;
        int i1 = r >> 3, j1 = r & 7;
        int my = idm[r];
        float sum = 0.f;
        #pragma unroll
        for (int c = 0; c < 32; c++) {
            int m = hf * 32 + c;
            float s = fmaf(Ss[r][m], scale,
                           sb[(i1 - (m >> 3) + 7) * 15 + (j1 - (m & 7) + 7)]);
            if (idm[m] != my) s -= 100.0f;
            float p = __expf(s);
            sum += p;
            Ps[r][m] = __float2bfloat16(p);
        }
        sum += __shfl_xor_sync(0xffffffffu, sum, 1);
        if (hf == 0) rinv[r] = 1.0f / sum;
    }
    __syncthreads();

    // ---- O = P V ----
    float* Os = &Ss[0][0];
    {
        wmma::fragment<wmma::matrix_a, 16, 16, 16, bf16, wmma::row_major> pa;
        wmma::fragment<wmma::matrix_b, 16, 16, 16, bf16, wmma::row_major> vb;
        wmma::fragment<wmma::accumulator, 16, 16, 16, float> oacc[2];
        #pragma unroll
        for (int nf = 0; nf < 2; nf++) wmma::fill_fragment(oacc[nf], 0.0f);
        #pragma unroll
        for (int kf = 0; kf < 4; kf++) {
            wmma::load_matrix_sync(pa, &Ps[w * 16][kf * 16], 72);
            #pragma unroll
            for (int nf = 0; nf < 2; nf++) {
                wmma::load_matrix_sync(vb, &Vs[kf * 16][nf * 16], 40);
                wmma::mma_sync(oacc[nf], pa, vb, oacc[nf]);
            }
        }
        #pragma unroll
        for (int nf = 0; nf < 2; nf++)
            wmma::store_matrix_sync(Os + (w * 16) * 36 + nf * 16, oacc[nf], 36,
                                    wmma::mem_row_major);
    }
    __syncthreads();

    // ---- epilogue: normalize + write bf16 ----
    {
        float inv = rinv[r];
        const float* orow = Os + r * 36 + hf * 16;
        bf16* outp = g_attnh + (size_t)(widx * 64 + r) * 256 + h * 32 + hf * 16;
        float o[16];
        *(float4*)(o)      = *(const float4*)(orow);
        *(float4*)(o + 4)  = *(const float4*)(orow + 4);
        *(float4*)(o + 8)  = *(const float4*)(orow + 8);
        *(float4*)(o + 12) = *(const float4*)(orow + 12);
        uint4 u0, u1;
        u0.x = packbf(o[0] * inv,  o[1] * inv);
        u0.y = packbf(o[2] * inv,  o[3] * inv);
        u0.z = packbf(o[4] * inv,  o[5] * inv);
        u0.w = packbf(o[6] * inv,  o[7] * inv);
        u1.x = packbf(o[8] * inv,  o[9] * inv);
        u1.y = packbf(o[10] * inv, o[11] * inv);
        u1.z = packbf(o[12] * inv, o[13] * inv);
        u1.w = packbf(o[14] * inv, o[15] * inv);
        *(uint4*)(outp)     = u0;
        *(uint4*)(outp + 8) = u1;
    }
}

// ---------------------------------------------------------------------------
// wmma bf16 GEMM: CTA 128x128, 4 warps (warp tile 64x64, 4x4 frags),
// BK=32, 3-stage cp.async pipeline (3 CTAs/SM), fused epilogue.
// MODE 0: g_qkvh     = bf16(A @ W + b)            N=768  K=256
// MODE 1: g_x1[perm] = x[perm] + gm*(A @ W + b)   N=256  K=256
// MODE 2: g_mlph     = bf16(gelu(A @ W + b))      N=1024 K=256
// MODE 3: out        = g_x1 + gp*(A @ W + b)      N=256  K=1024
// ---------------------------------------------------------------------------
#define AS_STR 40
#define BS_STR 136
#define STAGE_B (128 * AS_STR * 2 + 32 * BS_STR * 2)   // 18944
#define NSTAGE 3
#define GEMM_SMEM (NSTAGE * STAGE_B)                    // 56832

template <int MODE>
__global__ __launch_bounds__(128, 3)
void gemm_bf16(const float* __restrict__ bias,
               const float* __restrict__ xres,
               float* __restrict__ outp) {
    constexpr int K = (MODE == 3) ? 1024 : 256;
    constexpr int N = (MODE == 0) ? 768 : (MODE == 2) ? 1024 : 256;
    constexpr int NIT = K / 32;
    const bf16* A = (MODE == 0) ? g_hwinh : (MODE == 1) ? g_attnh
                  : (MODE == 2) ? g_h2h   : g_mlph;
    const bf16* W = g_wb + ((MODE == 0) ? WOFF_QKV : (MODE == 1) ? WOFF_PROJ
                         : (MODE == 2) ? WOFF_FC1 : WOFF_FC2);

    extern __shared__ char dsm[];
    int tid = threadIdx.x;
    int wid = tid >> 5;
    int wm = wid & 1;
    int wn = wid >> 1;
    int bm = blockIdx.y * 128, bn = blockIdx.x * 128;

    wmma::fragment<wmma::accumulator, 16, 16, 16, float> acc[4][4];
    #pragma unroll
    for (int mf = 0; mf < 4; mf++)
        #pragma unroll
        for (int nf = 0; nf < 4; nf++)
            wmma::fill_fragment(acc[mf][nf], 0.0f);

    const bf16* Abase = A + (size_t)bm * K;

    auto issue = [&](int it) {
        int buf = it % NSTAGE;
        bf16* As = (bf16*)(dsm + buf * STAGE_B);
        bf16* Bs = (bf16*)(dsm + buf * STAGE_B + 128 * AS_STR * 2);
        int k0 = it * 32;
        #pragma unroll
        for (int t = 0; t < 4; t++) {
            int idx = tid + t * 128;
            int r = idx >> 2, c = (idx & 3) * 8;
            __pipeline_memcpy_async(As + r * AS_STR + c,
                                    Abase + (size_t)r * K + k0 + c, 16);
        }
        #pragma unroll
        for (int t = 0; t < 4; t++) {
            int idx = tid + t * 128;
            int r = idx >> 4, c = (idx & 15) * 8;
            __pipeline_memcpy_async(Bs + r * BS_STR + c,
                                    W + (size_t)(k0 + r) * N + bn + c, 16);
        }
        __pipeline_commit();
    };

    issue(0);
    if (NIT > 1) issue(1);

    for (int it = 0; it < NIT; it++) {
        if (NIT - 1 - it >= 1) __pipeline_wait_prior(1);
        else                   __pipeline_wait_prior(0);
        __syncthreads();

        const bf16* As = (const bf16*)(dsm + (it % NSTAGE) * STAGE_B);
        const bf16* Bs = (const bf16*)(dsm + (it % NSTAGE) * STAGE_B + 128 * AS_STR * 2);
        #pragma unroll
        for (int kk = 0; kk < 32; kk += 16) {
            wmma::fragment<wmma::matrix_a, 16, 16, 16, bf16, wmma::row_major> af[4];
            wmma::fragment<wmma::matrix_b, 16, 16, 16, bf16, wmma::row_major> bf[4];
            #pragma unroll
            for (int mf = 0; mf < 4; mf++)
                wmma::load_matrix_sync(af[mf], As + (wm * 64 + mf * 16) * AS_STR + kk, AS_STR);
            #pragma unroll
            for (int nf = 0; nf < 4; nf++)
                wmma::load_matrix_sync(bf[nf], Bs + kk * BS_STR + wn * 64 + nf * 16, BS_STR);
            #pragma unroll
            for (int mf = 0; mf < 4; mf++)
                #pragma unroll
                for (int nf = 0; nf < 4; nf++)
                    wmma::mma_sync(acc[mf][nf], af[mf], bf[nf], acc[mf][nf]);
        }
        if (it + 2 < NIT) issue(it + 2);
    }
    __syncthreads();

    // ---- epilogue via smem roundtrip (alias stage buffers) ----
    // 128x128 fp32 = 64KB > 56.8KB smem, so do it in two half-tiles of 64 rows.
    float* epi = (float*)dsm;
    #pragma unroll
    for (int half = 0; half < 2; half++) {
        if (wm == half) {
            #pragma unroll
            for (int mf = 0; mf < 4; mf++)
                #pragma unroll
                for (int nf = 0; nf < 4; nf++)
                    wmma::store_matrix_sync(epi + (mf * 16) * 128 + wn * 64 + nf * 16,
                                            acc[mf][nf], 128, wmma::mem_row_major);
        }
        __syncthreads();

        #pragma unroll
        for (int t = 0; t < 8; t++) {
            int ch = tid + t * 128;           // 1024 chunks of 8 cols (64 rows)
            int r = ch >> 4;
            int c8 = (ch & 15) * 8;
            int col = bn + c8;
            int row = bm + half * 64 + r;
            float v[8];
            *(float4*)(v)     = *(const float4*)(epi + r * 128 + c8);
            *(float4*)(v + 4) = *(const float4*)(epi + r * 128 + c8 + 4);
            #pragma unroll
            for (int j = 0; j < 8; j++) v[j] += __ldg(&bias[col + j]);

            if (MODE == 0) {
                uint4 u;
                u.x = packbf(v[0], v[1]); u.y = packbf(v[2], v[3]);
                u.z = packbf(v[4], v[5]); u.w = packbf(v[6], v[7]);
                *(uint4*)(g_qkvh + (size_t)row * 768 + col) = u;
            } else if (MODE == 1) {
                int b = row >> 12, tt = row & 63, widx = (row >> 6) & 63;
                int wh = (widx >> 3) & 7, ww = widx & 7;
                int pr = (wh * 8 + (tt >> 3) + 4) & 63;
                int pc = (ww * 8 + (tt & 7) + 4) & 63;
                size_t prow = (size_t)(b * 4096 + pr * 64 + pc);
                const float* gm = g_ada + b * 1536 + 512;
                float o[8];
                #pragma unroll
                for (int j = 0; j < 8; j++)
                    o[j] = __ldg(&xres[prow * 256 + col + j]) + gm[col + j] * v[j];
                *(float4*)(g_x1 + prow * 256 + col)     = *(float4*)(o);
                *(float4*)(g_x1 + prow * 256 + col + 4) = *(float4*)(o + 4);
            } else if (MODE == 2) {
                uint4 u;
                float o[8];
                #pragma unroll
                for (int j = 0; j < 8; j++)
                    o[j] = 0.5f * v[j] * (1.0f + erff(v[j] * 0.70710678118654752f));
                u.x = packbf(o[0], o[1]); u.y = packbf(o[2], o[3]);
                u.z = packbf(o[4], o[5]); u.w = packbf(o[6], o[7]);
                *(uint4*)(g_mlph + (size_t)row * 1024 + col) = u;
            } else {
                int b = row >> 12;
                const float* gp = g_ada + b * 1536 + 1280;
                const float* x1 = g_x1 + (size_t)row * 256 + col;
                float o[8];
                #pragma unroll
                for (int j = 0; j < 8; j++)
                    o[j] = x1[j] + gp[col + j] * v[j];
                *(float4*)(outp + (size_t)row * 256 + col)     = *(float4*)(o);
                *(float4*)(outp + (size_t)row * 256 + col + 4) = *(float4*)(o + 4);
            }
        }
        if (half == 0) __syncthreads();
    }
}

// ---------------------------------------------------------------------------
extern "C" void kernel_launch(void* const* d_in, const int* in_sizes, int n_in,
                              void* d_out, int out_size) {
    const float* x       = (const float*)d_in[0];
    const float* cond    = (const float*)d_in[1];
    const float* norm1_g = (const float*)d_in[2];
    const float* norm1_b = (const float*)d_in[3];
    const float* w_qkv   = (const float*)d_in[4];
    const float* b_qkv   = (const float*)d_in[5];
    const float* rel_b   = (const float*)d_in[6];
    const float* w_proj  = (const float*)d_in[7];
    const float* b_proj  = (const float*)d_in[8];
    const float* norm2_g = (const float*)d_in[9];
    const float* norm2_b = (const float*)d_in[10];
    const float* w_fc1   = (const float*)d_in[11];
    const float* b_fc1   = (const float*)d_in[12];
    const float* w_fc2   = (const float*)d_in[13];
    const float* b_fc2   = (const float*)d_in[14];
    const float* w_ada   = (const float*)d_in[15];
    const float* b_ada   = (const float*)d_in[16];
    float* out = (float*)d_out;

    cudaFuncSetAttribute(gemm_bf16<0>, cudaFuncAttributeMaxDynamicSharedMemorySize, GEMM_SMEM);
    cudaFuncSetAttribute(gemm_bf16<1>, cudaFuncAttributeMaxDynamicSharedMemorySize, GEMM_SMEM);
    cudaFuncSetAttribute(gemm_bf16<2>, cudaFuncAttributeMaxDynamicSharedMemorySize, GEMM_SMEM);
    cudaFuncSetAttribute(gemm_bf16<3>, cudaFuncAttributeMaxDynamicSharedMemorySize, GEMM_SMEM);

    cvt_all_kernel<<<768, 256>>>(w_qkv, w_proj, w_fc1, w_fc2);
    ada_kernel<<<16, 256>>>(cond, w_ada, b_ada);
    ln_mod_kernel<0><<<8192, 256>>>(x, norm1_g, norm1_b);
    gemm_bf16<0><<<dim3(6, 512), 128, GEMM_SMEM>>>(b_qkv, nullptr, nullptr);
    attn_wmma_kernel<<<dim3(1024, 8), 128>>>(rel_b);
    gemm_bf16<1><<<dim3(2, 512), 128, GEMM_SMEM>>>(b_proj, x, nullptr);
    ln_mod_kernel<1><<<8192, 256>>>(nullptr, norm2_g, norm2_b);
    gemm_bf16<2><<<dim3(8, 512), 128, GEMM_SMEM>>>(b_fc1, nullptr, nullptr);
    gemm_bf16<3><<<dim3(2, 512), 128, GEMM_SMEM>>>(b_fc2, nullptr, out);
}

// round 16
// speedup vs baseline: 1.1350x; 1.0199x over previous
#include <cuda_runtime.h>
#include <cuda_bf16.h>
#include <cuda_pipeline_primitives.h>
#include <mma.h>
#include <math.h>

using namespace nvcuda;

// ---------------------------------------------------------------------------
// WITT AdaLN Swin block. wmma bf16 GEMMs (4-stage, 3 CTA/SM) + compact wmma attn.
// B=16, H=W=64, C=256, NH=8, HD=32, WS=8, SS=4, N=64, NWIN=64, MLP_H=1024.
// ---------------------------------------------------------------------------

#define TOK 65536
typedef __nv_bfloat16 bf16;

__device__ __align__(16) float g_ada  [16 * 1536];
__device__ __align__(16) bf16  g_wb   [786432];             // bf16 weights [K,N]
__device__ __align__(16) bf16  g_hwinh[(size_t)TOK * 256];
__device__ __align__(16) bf16  g_qkvh [(size_t)TOK * 768];
__device__ __align__(16) bf16  g_attnh[(size_t)TOK * 256];
__device__ __align__(16) float g_x1   [(size_t)TOK * 256];
__device__ __align__(16) bf16  g_h2h  [(size_t)TOK * 256];
__device__ __align__(16) bf16  g_mlph [(size_t)TOK * 1024];

#define WOFF_QKV  0
#define WOFF_PROJ 196608
#define WOFF_FC1  262144
#define WOFF_FC2  524288

__device__ __forceinline__ uint32_t packbf(float a, float b) {
    __nv_bfloat162 t = __floats2bfloat162_rn(a, b);
    return *reinterpret_cast<uint32_t*>(&t);
}

// ---------------------------------------------------------------------------
// all-weights fp32 -> bf16 (single launch). 196608 chunks of 4 floats.
// ---------------------------------------------------------------------------
__global__ void cvt_all_kernel(const float* __restrict__ w_qkv,
                               const float* __restrict__ w_proj,
                               const float* __restrict__ w_fc1,
                               const float* __restrict__ w_fc2) {
    int i = blockIdx.x * blockDim.x + threadIdx.x;
    const float* src; int off;
    if (i < 49152)       { src = w_qkv;  off = 0; }
    else if (i < 65536)  { src = w_proj; off = 49152; }
    else if (i < 131072) { src = w_fc1;  off = 65536; }
    else                 { src = w_fc2;  off = 131072; }
    float4 v = __ldg((const float4*)src + (i - off));
    uint2 u;
    u.x = packbf(v.x, v.y);
    u.y = packbf(v.z, v.w);
    *((uint2*)g_wb + i) = u;
}

// ---------------------------------------------------------------------------
// ada = silu(cond) @ w_ada + b_ada   [16,1536]
// ---------------------------------------------------------------------------
__global__ void ada_kernel(const float* __restrict__ cond,
                           const float* __restrict__ w_ada,
                           const float* __restrict__ b_ada) {
    __shared__ float sc[256];
    int b = blockIdx.x, t = threadIdx.x;
    float v = cond[b * 256 + t];
    sc[t] = v / (1.0f + expf(-v));
    __syncthreads();
    for (int j = t; j < 1536; j += 256) {
        float acc = b_ada[j];
        #pragma unroll 4
        for (int i = 0; i < 256; i++) acc = fmaf(sc[i], __ldg(&w_ada[i * 1536 + j]), acc);
        g_ada[b * 1536 + j] = acc;
    }
}

// ---------------------------------------------------------------------------
// LN + AdaLN -> bf16. PASS 0: roll(-4,-4)+window partition; PASS 1: plain.
// ---------------------------------------------------------------------------
template <int PASS>
__global__ void ln_mod_kernel(const float* __restrict__ xin,
                              const float* __restrict__ gamma,
                              const float* __restrict__ beta) {
    int gw   = (blockIdx.x * blockDim.x + threadIdx.x) >> 5;
    int lane = threadIdx.x & 31;
    int b = gw >> 12;

    const float* src;
    bf16* dst;
    if (PASS == 0) {
        int t = gw & 63, widx = (gw >> 6) & 63;
        int wh = (widx >> 3) & 7, ww = widx & 7;
        int sr  = (wh * 8 + (t >> 3) + 4) & 63;
        int sc2 = (ww * 8 + (t & 7) + 4) & 63;
        src = xin + ((size_t)(b * 4096 + sr * 64 + sc2)) * 256;
        dst = g_hwinh + (size_t)gw * 256;
    } else {
        src = g_x1 + (size_t)gw * 256;
        dst = g_h2h + (size_t)gw * 256;
    }

    float4 v0 = *(const float4*)(src + lane * 8);
    float4 v1 = *(const float4*)(src + lane * 8 + 4);
    float e[8] = {v0.x, v0.y, v0.z, v0.w, v1.x, v1.y, v1.z, v1.w};

    float s = 0.f, q = 0.f;
    #pragma unroll
    for (int j = 0; j < 8; j++) { s += e[j]; q += e[j] * e[j]; }
    #pragma unroll
    for (int off = 16; off > 0; off >>= 1) {
        s += __shfl_xor_sync(0xffffffffu, s, off);
        q += __shfl_xor_sync(0xffffffffu, q, off);
    }
    float mean = s * (1.0f / 256.0f);
    float var  = q * (1.0f / 256.0f) - mean * mean;
    float rstd = rsqrtf(var + 1e-5f);

    const float* scl = g_ada + b * 1536 + (PASS == 0 ? 256 : 1024);
    const float* sft = g_ada + b * 1536 + (PASS == 0 ? 0   : 768);

    int ch = lane * 8;
    float o[8];
    #pragma unroll
    for (int j = 0; j < 8; j++) {
        float y = (e[j] - mean) * rstd * __ldg(&gamma[ch + j]) + __ldg(&beta[ch + j]);
        o[j] = y * (1.0f + scl[ch + j]) + sft[ch + j];
    }
    uint4 u;
    u.x = packbf(o[0], o[1]); u.y = packbf(o[2], o[3]);
    u.z = packbf(o[4], o[5]); u.w = packbf(o[6], o[7]);
    *(uint4*)(dst + ch) = u;
}

// ---------------------------------------------------------------------------
// wmma attention: one block = one (window, head). 128 threads / 4 warps.
// Compact smem (34.3KB -> 6 CTAs/SM): Ps overlays dead Qs/Ks after S-phase.
// ---------------------------------------------------------------------------
__global__ __launch_bounds__(128)
void attn_wmma_kernel(const float* __restrict__ rel_bias) {
    // layout (bytes):
    //   [0,5120)      Qs [64][40] bf16      (dead after S)  } after softmax:
    //   [5120,10240)  Ks [64][40] bf16      (dead after S)  } Ps [64][72] bf16 at 0
    //   [10240,15360) Vs [64][40] bf16
    //   [15360,32768) Ss [64][68] float     (Os aliases, ldm 36)
    //   [32768,33668) sb [225] float
    //   [33668,33924) idm [64] int
    //   [33924,34180) rinv [64] float
    __shared__ __align__(16) char sm[34304];
    bf16*  Qs   = (bf16*)sm;
    bf16*  Ks   = (bf16*)(sm + 5120);
    bf16*  Ps   = (bf16*)sm;               // valid only after S-phase
    bf16*  Vs   = (bf16*)(sm + 10240);
    float* Ss   = (float*)(sm + 15360);
    float* Os   = Ss;                       // ldm 36
    float* sb   = (float*)(sm + 32768);
    int*   idm  = (int*)(sm + 33668);
    float* rinv = (float*)(sm + 33924);

    int widx = blockIdx.x;
    int h    = blockIdx.y;
    int tid  = threadIdx.x;
    int w    = tid >> 5;

    for (int i = tid; i < 225; i += 128) sb[i] = __ldg(&rel_bias[i * 8 + h]);
    if (tid < 64) {
        int wh = (widx >> 3) & 7, ww = widx & 7;
        int rv = wh * 8 + (tid >> 3), cv = ww * 8 + (tid & 7);
        idm[tid] = (rv < 56 ? 0 : (rv < 60 ? 1 : 2)) * 3 +
                   (cv < 56 ? 0 : (cv < 60 ? 1 : 2));
    }

    {
        int n = tid >> 1, hf = tid & 1;
        const bf16* rowp = g_qkvh + (size_t)widx * 64 * 768 + (size_t)n * 768 + h * 32;
        #pragma unroll
        for (int j = 0; j < 2; j++) {
            int c = hf * 16 + j * 8;
            *(uint4*)&Qs[n * 40 + c] = *(const uint4*)(rowp + c);
            *(uint4*)&Ks[n * 40 + c] = *(const uint4*)(rowp + 256 + c);
            *(uint4*)&Vs[n * 40 + c] = *(const uint4*)(rowp + 512 + c);
        }
    }
    __syncthreads();

    // ---- S = Q K^T ----
    {
        wmma::fragment<wmma::matrix_a, 16, 16, 16, bf16, wmma::row_major> a[2];
        wmma::fragment<wmma::matrix_b, 16, 16, 16, bf16, wmma::col_major> b;
        wmma::fragment<wmma::accumulator, 16, 16, 16, float> acc[4];
        #pragma unroll
        for (int nf = 0; nf < 4; nf++) wmma::fill_fragment(acc[nf], 0.0f);
        #pragma unroll
        for (int kf = 0; kf < 2; kf++)
            wmma::load_matrix_sync(a[kf], &Qs[(w * 16) * 40 + kf * 16], 40);
        #pragma unroll
        for (int kf = 0; kf < 2; kf++)
            #pragma unroll
            for (int nf = 0; nf < 4; nf++) {
                wmma::load_matrix_sync(b, &Ks[(nf * 16) * 40 + kf * 16], 40);
                wmma::mma_sync(acc[nf], a[kf], b, acc[nf]);
            }
        #pragma unroll
        for (int nf = 0; nf < 4; nf++)
            wmma::store_matrix_sync(&Ss[(w * 16) * 68 + nf * 16], acc[nf], 68,
                                    wmma::mem_row_major);
    }
    __syncthreads();

    // ---- softmax (unnormalized; scale fused). Ps overwrites Qs/Ks. ----
    int r = tid >> 1, hf = tid & 1;
    {
        const float scale = 0.17677669529663687f;
        int i1 = r >> 3, j1 = r & 7;
        int my = idm[r];
        float sum = 0.f;
        #pragma unroll
        for (int c = 0; c < 32; c++) {
            int m = hf * 32 + c;
            float s = fmaf(Ss[r * 68 + m], scale,
                           sb[(i1 - (m >> 3) + 7) * 15 + (j1 - (m & 7) + 7)]);
            if (idm[m] != my) s -= 100.0f;
            float p = __expf(s);
            sum += p;
            Ps[r * 72 + m] = __float2bfloat16(p);
        }
        sum += __shfl_xor_sync(0xffffffffu, sum, 1);
        if (hf == 0) rinv[r] = 1.0f / sum;
    }
    __syncthreads();

    // ---- O = P V ----  (Os aliases Ss, ldm 36)
    {
        wmma::fragment<wmma::matrix_a, 16, 16, 16, bf16, wmma::row_major> pa;
        wmma::fragment<wmma::matrix_b, 16, 16, 16, bf16, wmma::row_major> vb;
        wmma::fragment<wmma::accumulator, 16, 16, 16, float> oacc[2];
        #pragma unroll
        for (int nf = 0; nf < 2; nf++) wmma::fill_fragment(oacc[nf], 0.0f);
        #pragma unroll
        for (int kf = 0; kf < 4; kf++) {
            wmma::load_matrix_sync(pa, &Ps[(w * 16) * 72 + kf * 16], 72);
            #pragma unroll
            for (int nf = 0; nf < 2; nf++) {
                wmma::load_matrix_sync(vb, &Vs[(kf * 16) * 40 + nf * 16], 40);
                wmma::mma_sync(oacc[nf], pa, vb, oacc[nf]);
            }
        }
        #pragma unroll
        for (int nf = 0; nf < 2; nf++)
            wmma::store_matrix_sync(Os + (w * 16) * 36 + nf * 16, oacc[nf], 36,
                                    wmma::mem_row_major);
    }
    __syncthreads();

    // ---- epilogue: normalize + write bf16 ----
    {
        float inv = rinv[r];
        const float* orow = Os + r * 36 + hf * 16;
        bf16* outp = g_attnh + (size_t)(widx * 64 + r) * 256 + h * 32 + hf * 16;
        float o[16];
        *(float4*)(o)      = *(const float4*)(orow);
        *(float4*)(o + 4)  = *(const float4*)(orow + 4);
        *(float4*)(o + 8)  = *(const float4*)(orow + 8);
        *(float4*)(o + 12) = *(const float4*)(orow + 12);
        uint4 u0, u1;
        u0.x = packbf(o[0] * inv,  o[1] * inv);
        u0.y = packbf(o[2] * inv,  o[3] * inv);
        u0.z = packbf(o[4] * inv,  o[5] * inv);
        u0.w = packbf(o[6] * inv,  o[7] * inv);
        u1.x = packbf(o[8] * inv,  o[9] * inv);
        u1.y = packbf(o[10] * inv, o[11] * inv);
        u1.z = packbf(o[12] * inv, o[13] * inv);
        u1.w = packbf(o[14] * inv, o[15] * inv);
        *(uint4*)(outp)     = u0;
        *(uint4*)(outp + 8) = u1;
    }
}

// ---------------------------------------------------------------------------
// wmma bf16 GEMM: CTA 128x128, 4 warps (warp tile 64x64, 4x4 frags),
// BK=32, 4-stage cp.async pipeline at 3 CTAs/SM (227.3KB), full-tile epilogue.
// MODE 0: g_qkvh     = bf16(A @ W + b)            N=768  K=256
// MODE 1: g_x1[perm] = x[perm] + gm*(A @ W + b)   N=256  K=256
// MODE 2: g_mlph     = bf16(gelu(A @ W + b))      N=1024 K=256
// MODE 3: out        = g_x1 + gp*(A @ W + b)      N=256  K=1024
// ---------------------------------------------------------------------------
#define AS_STR 40
#define BS_STR 136
#define STAGE_B (128 * AS_STR * 2 + 32 * BS_STR * 2)   // 18944
#define NSTAGE 4
#define GEMM_SMEM (NSTAGE * STAGE_B)                    // 75776

template <int MODE>
__global__ __launch_bounds__(128, 3)
void gemm_bf16(const float* __restrict__ bias,
               const float* __restrict__ xres,
               float* __restrict__ outp) {
    constexpr int K = (MODE == 3) ? 1024 : 256;
    constexpr int N = (MODE == 0) ? 768 : (MODE == 2) ? 1024 : 256;
    constexpr int NIT = K / 32;
    const bf16* A = (MODE == 0) ? g_hwinh : (MODE == 1) ? g_attnh
                  : (MODE == 2) ? g_h2h   : g_mlph;
    const bf16* W = g_wb + ((MODE == 0) ? WOFF_QKV : (MODE == 1) ? WOFF_PROJ
                         : (MODE == 2) ? WOFF_FC1 : WOFF_FC2);

    extern __shared__ char dsm[];
    int tid = threadIdx.x;
    int wid = tid >> 5;
    int wm = wid & 1;
    int wn = wid >> 1;
    int bm = blockIdx.y * 128, bn = blockIdx.x * 128;

    wmma::fragment<wmma::accumulator, 16, 16, 16, float> acc[4][4];
    #pragma unroll
    for (int mf = 0; mf < 4; mf++)
        #pragma unroll
        for (int nf = 0; nf < 4; nf++)
            wmma::fill_fragment(acc[mf][nf], 0.0f);

    const bf16* Abase = A + (size_t)bm * K;

    auto issue = [&](int it) {
        int buf = it & 3;
        bf16* As = (bf16*)(dsm + buf * STAGE_B);
        bf16* Bs = (bf16*)(dsm + buf * STAGE_B + 128 * AS_STR * 2);
        int k0 = it * 32;
        #pragma unroll
        for (int t = 0; t < 4; t++) {
            int idx = tid + t * 128;
            int r = idx >> 2, c = (idx & 3) * 8;
            __pipeline_memcpy_async(As + r * AS_STR + c,
                                    Abase + (size_t)r * K + k0 + c, 16);
        }
        #pragma unroll
        for (int t = 0; t < 4; t++) {
            int idx = tid + t * 128;
            int r = idx >> 4, c = (idx & 15) * 8;
            __pipeline_memcpy_async(Bs + r * BS_STR + c,
                                    W + (size_t)(k0 + r) * N + bn + c, 16);
        }
        __pipeline_commit();
    };

    issue(0);
    if (NIT > 1) issue(1);
    if (NIT > 2) issue(2);

    for (int it = 0; it < NIT; it++) {
        if (NIT - 1 - it >= 2)      __pipeline_wait_prior(2);
        else if (NIT - 1 - it == 1) __pipeline_wait_prior(1);
        else                        __pipeline_wait_prior(0);
        __syncthreads();

        const bf16* As = (const bf16*)(dsm + (it & 3) * STAGE_B);
        const bf16* Bs = (const bf16*)(dsm + (it & 3) * STAGE_B + 128 * AS_STR * 2);
        #pragma unroll
        for (int kk = 0; kk < 32; kk += 16) {
            wmma::fragment<wmma::matrix_a, 16, 16, 16, bf16, wmma::row_major> af[4];
            wmma::fragment<wmma::matrix_b, 16, 16, 16, bf16, wmma::row_major> bf[4];
            #pragma unroll
            for (int mf = 0; mf < 4; mf++)
                wmma::load_matrix_sync(af[mf], As + (wm * 64 + mf * 16) * AS_STR + kk, AS_STR);
            #pragma unroll
            for (int nf = 0; nf < 4; nf++)
                wmma::load_matrix_sync(bf[nf], Bs + kk * BS_STR + wn * 64 + nf * 16, BS_STR);
            #pragma unroll
            for (int mf = 0; mf < 4; mf++)
                #pragma unroll
                for (int nf = 0; nf < 4; nf++)
                    wmma::mma_sync(acc[mf][nf], af[mf], bf[nf], acc[mf][nf]);
        }
        if (it + 3 < NIT) issue(it + 3);
    }
    __syncthreads();

    // ---- epilogue via smem roundtrip (alias stage buffers: 64KB fp32) ----
    float* epi = (float*)dsm;
    #pragma unroll
    for (int mf = 0; mf < 4; mf++)
        #pragma unroll
        for (int nf = 0; nf < 4; nf++)
            wmma::store_matrix_sync(epi + (wm * 64 + mf * 16) * 128 + wn * 64 + nf * 16,
                                    acc[mf][nf], 128, wmma::mem_row_major);
    __syncthreads();

    #pragma unroll
    for (int t = 0; t < 16; t++) {
        int ch = tid + t * 128;
        int r = ch >> 4;
        int c8 = (ch & 15) * 8;
        int col = bn + c8;
        int row = bm + r;
        float v[8];
        *(float4*)(v)     = *(const float4*)(epi + r * 128 + c8);
        *(float4*)(v + 4) = *(const float4*)(epi + r * 128 + c8 + 4);
        #pragma unroll
        for (int j = 0; j < 8; j++) v[j] += __ldg(&bias[col + j]);

        if (MODE == 0) {
            uint4 u;
            u.x = packbf(v[0], v[1]); u.y = packbf(v[2], v[3]);
            u.z = packbf(v[4], v[5]); u.w = packbf(v[6], v[7]);
            *(uint4*)(g_qkvh + (size_t)row * 768 + col) = u;
        } else if (MODE == 1) {
            int b = row >> 12, tt = row & 63, widx = (row >> 6) & 63;
            int wh = (widx >> 3) & 7, ww = widx & 7;
            int pr = (wh * 8 + (tt >> 3) + 4) & 63;
            int pc = (ww * 8 + (tt & 7) + 4) & 63;
            size_t prow = (size_t)(b * 4096 + pr * 64 + pc);
            const float* gm = g_ada + b * 1536 + 512;
            float o[8];
            #pragma unroll
            for (int j = 0; j < 8; j++)
                o[j] = __ldg(&xres[prow * 256 + col + j]) + gm[col + j] * v[j];
            *(float4*)(g_x1 + prow * 256 + col)     = *(float4*)(o);
            *(float4*)(g_x1 + prow * 256 + col + 4) = *(float4*)(o + 4);
        } else if (MODE == 2) {
            uint4 u;
            float o[8];
            #pragma unroll
            for (int j = 0; j < 8; j++)
                o[j] = 0.5f * v[j] * (1.0f + erff(v[j] * 0.70710678118654752f));
            u.x = packbf(o[0], o[1]); u.y = packbf(o[2], o[3]);
            u.z = packbf(o[4], o[5]); u.w = packbf(o[6], o[7]);
            *(uint4*)(g_mlph + (size_t)row * 1024 + col) = u;
        } else {
            int b = row >> 12;
            const float* gp = g_ada + b * 1536 + 1280;
            const float* x1 = g_x1 + (size_t)row * 256 + col;
            float o[8];
            #pragma unroll
            for (int j = 0; j < 8; j++)
                o[j] = x1[j] + gp[col + j] * v[j];
            *(float4*)(outp + (size_t)row * 256 + col)     = *(float4*)(o);
            *(float4*)(outp + (size_t)row * 256 + col + 4) = *(float4*)(o + 4);
        }
    }
}

// ---------------------------------------------------------------------------
extern "C" void kernel_launch(void* const* d_in, const int* in_sizes, int n_in,
                              void* d_out, int out_size) {
    const float* x       = (const float*)d_in[0];
    const float* cond    = (const float*)d_in[1];
    const float* norm1_g = (const float*)d_in[2];
    const float* norm1_b = (const float*)d_in[3];
    const float* w_qkv   = (const float*)d_in[4];
    const float* b_qkv   = (const float*)d_in[5];
    const float* rel_b   = (const float*)d_in[6];
    const float* w_proj  = (const float*)d_in[7];
    const float* b_proj  = (const float*)d_in[8];
    const float* norm2_g = (const float*)d_in[9];
    const float* norm2_b = (const float*)d_in[10];
    const float* w_fc1   = (const float*)d_in[11];
    const float* b_fc1   = (const float*)d_in[12];
    const float* w_fc2   = (const float*)d_in[13];
    const float* b_fc2   = (const float*)d_in[14];
    const float* w_ada   = (const float*)d_in[15];
    const float* b_ada   = (const float*)d_in[16];
    float* out = (float*)d_out;

    cudaFuncSetAttribute(gemm_bf16<0>, cudaFuncAttributeMaxDynamicSharedMemorySize, GEMM_SMEM);
    cudaFuncSetAttribute(gemm_bf16<1>, cudaFuncAttributeMaxDynamicSharedMemorySize, GEMM_SMEM);
    cudaFuncSetAttribute(gemm_bf16<2>, cudaFuncAttributeMaxDynamicSharedMemorySize, GEMM_SMEM);
    cudaFuncSetAttribute(gemm_bf16<3>, cudaFuncAttributeMaxDynamicSharedMemorySize, GEMM_SMEM);

    cvt_all_kernel<<<768, 256>>>(w_qkv, w_proj, w_fc1, w_fc2);
    ada_kernel<<<16, 256>>>(cond, w_ada, b_ada);
    ln_mod_kernel<0><<<8192, 256>>>(x, norm1_g, norm1_b);
    gemm_bf16<0><<<dim3(6, 512), 128, GEMM_SMEM>>>(b_qkv, nullptr, nullptr);
    attn_wmma_kernel<<<dim3(1024, 8), 128>>>(rel_b);
    gemm_bf16<1><<<dim3(2, 512), 128, GEMM_SMEM>>>(b_proj, x, nullptr);
    ln_mod_kernel<1><<<8192, 256>>>(nullptr, norm2_g, norm2_b);
    gemm_bf16<2><<<dim3(8, 512), 128, GEMM_SMEM>>>(b_fc1, nullptr, nullptr);
    gemm_bf16<3><<<dim3(2, 512), 128, GEMM_SMEM>>>(b_fc2, nullptr, out);
}

// round 17
// speedup vs baseline: 1.1486x; 1.0120x over previous
#include <cuda_runtime.h>
#include <cuda_bf16.h>
#include <cuda_pipeline_primitives.h>
#include <mma.h>
#include <math.h>

using namespace nvcuda;

// ---------------------------------------------------------------------------
// WITT AdaLN Swin block. wmma bf16 GEMMs + compact wmma attn.
// proj-GEMM uses 64x256 tile with fused LN2 epilogue (ln_mod<1> eliminated).
// B=16, H=W=64, C=256, NH=8, HD=32, WS=8, SS=4, N=64, NWIN=64, MLP_H=1024.
// ---------------------------------------------------------------------------

#define TOK 65536
typedef __nv_bfloat16 bf16;

__device__ __align__(16) float g_ada  [16 * 1536];
__device__ __align__(16) bf16  g_wb   [786432];             // bf16 weights [K,N]
__device__ __align__(16) bf16  g_hwinh[(size_t)TOK * 256];
__device__ __align__(16) bf16  g_qkvh [(size_t)TOK * 768];
__device__ __align__(16) bf16  g_attnh[(size_t)TOK * 256];
__device__ __align__(16) float g_x1   [(size_t)TOK * 256];
__device__ __align__(16) bf16  g_h2h  [(size_t)TOK * 256];
__device__ __align__(16) bf16  g_mlph [(size_t)TOK * 1024];

#define WOFF_QKV  0
#define WOFF_PROJ 196608
#define WOFF_FC1  262144
#define WOFF_FC2  524288

__device__ __forceinline__ uint32_t packbf(float a, float b) {
    __nv_bfloat162 t = __floats2bfloat162_rn(a, b);
    return *reinterpret_cast<uint32_t*>(&t);
}

// ---------------------------------------------------------------------------
__global__ void cvt_all_kernel(const float* __restrict__ w_qkv,
                               const float* __restrict__ w_proj,
                               const float* __restrict__ w_fc1,
                               const float* __restrict__ w_fc2) {
    int i = blockIdx.x * blockDim.x + threadIdx.x;
    const float* src; int off;
    if (i < 49152)       { src = w_qkv;  off = 0; }
    else if (i < 65536)  { src = w_proj; off = 49152; }
    else if (i < 131072) { src = w_fc1;  off = 65536; }
    else                 { src = w_fc2;  off = 131072; }
    float4 v = __ldg((const float4*)src + (i - off));
    uint2 u;
    u.x = packbf(v.x, v.y);
    u.y = packbf(v.z, v.w);
    *((uint2*)g_wb + i) = u;
}

// ---------------------------------------------------------------------------
__global__ void ada_kernel(const float* __restrict__ cond,
                           const float* __restrict__ w_ada,
                           const float* __restrict__ b_ada) {
    __shared__ float sc[256];
    int b = blockIdx.x, t = threadIdx.x;
    float v = cond[b * 256 + t];
    sc[t] = v / (1.0f + expf(-v));
    __syncthreads();
    for (int j = t; j < 1536; j += 256) {
        float acc = b_ada[j];
        #pragma unroll 4
        for (int i = 0; i < 256; i++) acc = fmaf(sc[i], __ldg(&w_ada[i * 1536 + j]), acc);
        g_ada[b * 1536 + j] = acc;
    }
}

// ---------------------------------------------------------------------------
// LN1 + AdaLN -> bf16 with roll(-4,-4)+window partition.
// ---------------------------------------------------------------------------
__global__ void ln_mod0_kernel(const float* __restrict__ xin,
                               const float* __restrict__ gamma,
                               const float* __restrict__ beta) {
    int gw   = (blockIdx.x * blockDim.x + threadIdx.x) >> 5;
    int lane = threadIdx.x & 31;
    int b = gw >> 12;

    int t = gw & 63, widx = (gw >> 6) & 63;
    int wh = (widx >> 3) & 7, ww = widx & 7;
    int sr  = (wh * 8 + (t >> 3) + 4) & 63;
    int sc2 = (ww * 8 + (t & 7) + 4) & 63;
    const float* src = xin + ((size_t)(b * 4096 + sr * 64 + sc2)) * 256;
    bf16* dst = g_hwinh + (size_t)gw * 256;

    float4 v0 = *(const float4*)(src + lane * 8);
    float4 v1 = *(const float4*)(src + lane * 8 + 4);
    float e[8] = {v0.x, v0.y, v0.z, v0.w, v1.x, v1.y, v1.z, v1.w};

    float s = 0.f, q = 0.f;
    #pragma unroll
    for (int j = 0; j < 8; j++) { s += e[j]; q += e[j] * e[j]; }
    #pragma unroll
    for (int off = 16; off > 0; off >>= 1) {
        s += __shfl_xor_sync(0xffffffffu, s, off);
        q += __shfl_xor_sync(0xffffffffu, q, off);
    }
    float mean = s * (1.0f / 256.0f);
    float var  = q * (1.0f / 256.0f) - mean * mean;
    float rstd = rsqrtf(var + 1e-5f);

    const float* scl = g_ada + b * 1536 + 256;  // cm
    const float* sft = g_ada + b * 1536 + 0;    // sm

    int ch = lane * 8;
    float o[8];
    #pragma unroll
    for (int j = 0; j < 8; j++) {
        float y = (e[j] - mean) * rstd * __ldg(&gamma[ch + j]) + __ldg(&beta[ch + j]);
        o[j] = y * (1.0f + scl[ch + j]) + sft[ch + j];
    }
    uint4 u;
    u.x = packbf(o[0], o[1]); u.y = packbf(o[2], o[3]);
    u.z = packbf(o[4], o[5]); u.w = packbf(o[6], o[7]);
    *(uint4*)(dst + ch) = u;
}

// ---------------------------------------------------------------------------
// wmma attention (compact smem, 6 CTAs/SM).
// ---------------------------------------------------------------------------
__global__ __launch_bounds__(128)
void attn_wmma_kernel(const float* __restrict__ rel_bias) {
    __shared__ __align__(16) char sm[34304];
    bf16*  Qs   = (bf16*)sm;
    bf16*  Ks   = (bf16*)(sm + 5120);
    bf16*  Ps   = (bf16*)sm;               // valid only after S-phase
    bf16*  Vs   = (bf16*)(sm + 10240);
    float* Ss   = (float*)(sm + 15360);
    float* Os   = Ss;                       // ldm 36
    float* sb   = (float*)(sm + 32768);
    int*   idm  = (int*)(sm + 33668);
    float* rinv = (float*)(sm + 33924);

    int widx = blockIdx.x;
    int h    = blockIdx.y;
    int tid  = threadIdx.x;
    int w    = tid >> 5;

    for (int i = tid; i < 225; i += 128) sb[i] = __ldg(&rel_bias[i * 8 + h]);
    if (tid < 64) {
        int wh = (widx >> 3) & 7, ww = widx & 7;
        int rv = wh * 8 + (tid >> 3), cv = ww * 8 + (tid & 7);
        idm[tid] = (rv < 56 ? 0 : (rv < 60 ? 1 : 2)) * 3 +
                   (cv < 56 ? 0 : (cv < 60 ? 1 : 2));
    }

    {
        int n = tid >> 1, hf = tid & 1;
        const bf16* rowp = g_qkvh + (size_t)widx * 64 * 768 + (size_t)n * 768 + h * 32;
        #pragma unroll
        for (int j = 0; j < 2; j++) {
            int c = hf * 16 + j * 8;
            *(uint4*)&Qs[n * 40 + c] = *(const uint4*)(rowp + c);
            *(uint4*)&Ks[n * 40 + c] = *(const uint4*)(rowp + 256 + c);
            *(uint4*)&Vs[n * 40 + c] = *(const uint4*)(rowp + 512 + c);
        }
    }
    __syncthreads();

    {
        wmma::fragment<wmma::matrix_a, 16, 16, 16, bf16, wmma::row_major> a[2];
        wmma::fragment<wmma::matrix_b, 16, 16, 16, bf16, wmma::col_major> b;
        wmma::fragment<wmma::accumulator, 16, 16, 16, float> acc[4];
        #pragma unroll
        for (int nf = 0; nf < 4; nf++) wmma::fill_fragment(acc[nf], 0.0f);
        #pragma unroll
        for (int kf = 0; kf < 2; kf++)
            wmma::load_matrix_sync(a[kf], &Qs[(w * 16) * 40 + kf * 16], 40);
        #pragma unroll
        for (int kf = 0; kf < 2; kf++)
            #pragma unroll
            for (int nf = 0; nf < 4; nf++) {
                wmma::load_matrix_sync(b, &Ks[(nf * 16) * 40 + kf * 16], 40);
                wmma::mma_sync(acc[nf], a[kf], b, acc[nf]);
            }
        #pragma unroll
        for (int nf = 0; nf < 4; nf++)
            wmma::store_matrix_sync(&Ss[(w * 16) * 68 + nf * 16], acc[nf], 68,
                                    wmma::mem_row_major);
    }
    __syncthreads();

    int r = tid >> 1, hf = tid & 1;
    {
        const float scale = 0.17677669529663687f;
        int i1 = r >> 3, j1 = r & 7;
        int my = idm[r];
        float sum = 0.f;
        #pragma unroll
        for (int c = 0; c < 32; c++) {
            int m = hf * 32 + c;
            float s = fmaf(Ss[r * 68 + m], scale,
                           sb[(i1 - (m >> 3) + 7) * 15 + (j1 - (m & 7) + 7)]);
            if (idm[m] != my) s -= 100.0f;
            float p = __expf(s);
            sum += p;
            Ps[r * 72 + m] = __float2bfloat16(p);
        }
        sum += __shfl_xor_sync(0xffffffffu, sum, 1);
        if (hf == 0) rinv[r] = 1.0f / sum;
    }
    __syncthreads();

    {
        wmma::fragment<wmma::matrix_a, 16, 16, 16, bf16, wmma::row_major> pa;
        wmma::fragment<wmma::matrix_b, 16, 16, 16, bf16, wmma::row_major> vb;
        wmma::fragment<wmma::accumulator, 16, 16, 16, float> oacc[2];
        #pragma unroll
        for (int nf = 0; nf < 2; nf++) wmma::fill_fragment(oacc[nf], 0.0f);
        #pragma unroll
        for (int kf = 0; kf < 4; kf++) {
            wmma::load_matrix_sync(pa, &Ps[(w * 16) * 72 + kf * 16], 72);
            #pragma unroll
            for (int nf = 0; nf < 2; nf++) {
                wmma::load_matrix_sync(vb, &Vs[(kf * 16) * 40 + nf * 16], 40);
                wmma::mma_sync(oacc[nf], pa, vb, oacc[nf]);
            }
        }
        #pragma unroll
        for (int nf = 0; nf < 2; nf++)
            wmma::store_matrix_sync(Os + (w * 16) * 36 + nf * 16, oacc[nf], 36,
                                    wmma::mem_row_major);
    }
    __syncthreads();

    {
        float inv = rinv[r];
        const float* orow = Os + r * 36 + hf * 16;
        bf16* outp = g_attnh + (size_t)(widx * 64 + r) * 256 + h * 32 + hf * 16;
        float o[16];
        *(float4*)(o)      = *(const float4*)(orow);
        *(float4*)(o + 4)  = *(const float4*)(orow + 4);
        *(float4*)(o + 8)  = *(const float4*)(orow + 8);
        *(float4*)(o + 12) = *(const float4*)(orow + 12);
        uint4 u0, u1;
        u0.x = packbf(o[0] * inv,  o[1] * inv);
        u0.y = packbf(o[2] * inv,  o[3] * inv);
        u0.z = packbf(o[4] * inv,  o[5] * inv);
        u0.w = packbf(o[6] * inv,  o[7] * inv);
        u1.x = packbf(o[8] * inv,  o[9] * inv);
        u1.y = packbf(o[10] * inv, o[11] * inv);
        u1.z = packbf(o[12] * inv, o[13] * inv);
        u1.w = packbf(o[14] * inv, o[15] * inv);
        *(uint4*)(outp)     = u0;
        *(uint4*)(outp + 8) = u1;
    }
}

// ---------------------------------------------------------------------------
// Generic wmma GEMM (MODE 0/2/3): CTA 128x128, 4 warps 64x64, BK=32, 4-stage.
// MODE 0: g_qkvh = bf16(A@W + b)            N=768  K=256
// MODE 2: g_mlph = bf16(gelu(A@W + b))      N=1024 K=256
// MODE 3: out    = g_x1 + gp*(A@W + b)      N=256  K=1024
// ---------------------------------------------------------------------------
#define AS_STR 40
#define BS_STR 136
#define STAGE_B (128 * AS_STR * 2 + 32 * BS_STR * 2)   // 18944
#define GEMM_SMEM (4 * STAGE_B)                         // 75776

template <int MODE>
__global__ __launch_bounds__(128, 3)
void gemm_bf16(const float* __restrict__ bias,
               float* __restrict__ outp) {
    constexpr int K = (MODE == 3) ? 1024 : 256;
    constexpr int N = (MODE == 0) ? 768 : (MODE == 2) ? 1024 : 256;
    constexpr int NIT = K / 32;
    const bf16* A = (MODE == 0) ? g_hwinh : (MODE == 2) ? g_h2h : g_mlph;
    const bf16* W = g_wb + ((MODE == 0) ? WOFF_QKV : (MODE == 2) ? WOFF_FC1 : WOFF_FC2);

    extern __shared__ char dsm[];
    int tid = threadIdx.x;
    int wid = tid >> 5;
    int wm = wid & 1;
    int wn = wid >> 1;
    int bm = blockIdx.y * 128, bn = blockIdx.x * 128;

    wmma::fragment<wmma::accumulator, 16, 16, 16, float> acc[4][4];
    #pragma unroll
    for (int mf = 0; mf < 4; mf++)
        #pragma unroll
        for (int nf = 0; nf < 4; nf++)
            wmma::fill_fragment(acc[mf][nf], 0.0f);

    const bf16* Abase = A + (size_t)bm * K;

    auto issue = [&](int it) {
        int buf = it & 3;
        bf16* As = (bf16*)(dsm + buf * STAGE_B);
        bf16* Bs = (bf16*)(dsm + buf * STAGE_B + 128 * AS_STR * 2);
        int k0 = it * 32;
        #pragma unroll
        for (int t = 0; t < 4; t++) {
            int idx = tid + t * 128;
            int r = idx >> 2, c = (idx & 3) * 8;
            __pipeline_memcpy_async(As + r * AS_STR + c,
                                    Abase + (size_t)r * K + k0 + c, 16);
        }
        #pragma unroll
        for (int t = 0; t < 4; t++) {
            int idx = tid + t * 128;
            int r = idx >> 4, c = (idx & 15) * 8;
            __pipeline_memcpy_async(Bs + r * BS_STR + c,
                                    W + (size_t)(k0 + r) * N + bn + c, 16);
        }
        __pipeline_commit();
    };

    issue(0);
    if (NIT > 1) issue(1);
    if (NIT > 2) issue(2);

    for (int it = 0; it < NIT; it++) {
        if (NIT - 1 - it >= 2)      __pipeline_wait_prior(2);
        else if (NIT - 1 - it == 1) __pipeline_wait_prior(1);
        else                        __pipeline_wait_prior(0);
        __syncthreads();

        const bf16* As = (const bf16*)(dsm + (it & 3) * STAGE_B);
        const bf16* Bs = (const bf16*)(dsm + (it & 3) * STAGE_B + 128 * AS_STR * 2);
        #pragma unroll
        for (int kk = 0; kk < 32; kk += 16) {
            wmma::fragment<wmma::matrix_a, 16, 16, 16, bf16, wmma::row_major> af[4];
            wmma::fragment<wmma::matrix_b, 16, 16, 16, bf16, wmma::row_major> bf[4];
            #pragma unroll
            for (int mf = 0; mf < 4; mf++)
                wmma::load_matrix_sync(af[mf], As + (wm * 64 + mf * 16) * AS_STR + kk, AS_STR);
            #pragma unroll
            for (int nf = 0; nf < 4; nf++)
                wmma::load_matrix_sync(bf[nf], Bs + kk * BS_STR + wn * 64 + nf * 16, BS_STR);
            #pragma unroll
            for (int mf = 0; mf < 4; mf++)
                #pragma unroll
                for (int nf = 0; nf < 4; nf++)
                    wmma::mma_sync(acc[mf][nf], af[mf], bf[nf], acc[mf][nf]);
        }
        if (it + 3 < NIT) issue(it + 3);
    }
    __syncthreads();

    float* epi = (float*)dsm;
    #pragma unroll
    for (int mf = 0; mf < 4; mf++)
        #pragma unroll
        for (int nf = 0; nf < 4; nf++)
            wmma::store_matrix_sync(epi + (wm * 64 + mf * 16) * 128 + wn * 64 + nf * 16,
                                    acc[mf][nf], 128, wmma::mem_row_major);
    __syncthreads();

    #pragma unroll
    for (int t = 0; t < 16; t++) {
        int ch = tid + t * 128;
        int r = ch >> 4;
        int c8 = (ch & 15) * 8;
        int col = bn + c8;
        int row = bm + r;
        float v[8];
        *(float4*)(v)     = *(const float4*)(epi + r * 128 + c8);
        *(float4*)(v + 4) = *(const float4*)(epi + r * 128 + c8 + 4);
        #pragma unroll
        for (int j = 0; j < 8; j++) v[j] += __ldg(&bias[col + j]);

        if (MODE == 0) {
            uint4 u;
            u.x = packbf(v[0], v[1]); u.y = packbf(v[2], v[3]);
            u.z = packbf(v[4], v[5]); u.w = packbf(v[6], v[7]);
            *(uint4*)(g_qkvh + (size_t)row * 768 + col) = u;
        } else if (MODE == 2) {
            uint4 u;
            float o[8];
            #pragma unroll
            for (int j = 0; j < 8; j++)
                o[j] = 0.5f * v[j] * (1.0f + erff(v[j] * 0.70710678118654752f));
            u.x = packbf(o[0], o[1]); u.y = packbf(o[2], o[3]);
            u.z = packbf(o[4], o[5]); u.w = packbf(o[6], o[7]);
            *(uint4*)(g_mlph + (size_t)row * 1024 + col) = u;
        } else {
            int b = row >> 12;
            const float* gp = g_ada + b * 1536 + 1280;
            const float* x1 = g_x1 + (size_t)row * 256 + col;
            float o[8];
            #pragma unroll
            for (int j = 0; j < 8; j++)
                o[j] = x1[j] + gp[col + j] * v[j];
            *(float4*)(outp + (size_t)row * 256 + col)     = *(float4*)(o);
            *(float4*)(outp + (size_t)row * 256 + col + 4) = *(float4*)(o + 4);
        }
    }
}

// ---------------------------------------------------------------------------
// proj GEMM with fused LN2: CTA 64x256 (full N), 4 warps 64x64, BK=32, 3-stage.
// epilogue: g_x1[perm] = x[perm] + gm*(A@Wproj + b);  then LN2+mod -> g_h2h.
// ---------------------------------------------------------------------------
#define P_AS_STR 40
#define P_BS_STR 264
#define P_STAGE_B (64 * P_AS_STR * 2 + 32 * P_BS_STR * 2)   // 5120+16896=22016
#define P_GEMM_SMEM (3 * P_STAGE_B)                          // 66048

__global__ __launch_bounds__(128, 3)
void gemm_proj_ln(const float* __restrict__ bias,
                  const float* __restrict__ xres,
                  const float* __restrict__ gamma,
                  const float* __restrict__ beta) {
    constexpr int K = 256;
    constexpr int NIT = 8;
    const bf16* W = g_wb + WOFF_PROJ;   // [256,256]

    extern __shared__ char dsm[];
    int tid = threadIdx.x;
    int wid = tid >> 5;
    int lane = tid & 31;
    int wn = wid;                       // cols wn*64
    int bm = blockIdx.x * 64;

    wmma::fragment<wmma::accumulator, 16, 16, 16, float> acc[4][4];
    #pragma unroll
    for (int mf = 0; mf < 4; mf++)
        #pragma unroll
        for (int nf = 0; nf < 4; nf++)
            wmma::fill_fragment(acc[mf][nf], 0.0f);

    const bf16* Abase = g_attnh + (size_t)bm * K;

    auto issue = [&](int it) {
        int buf = it % 3;
        bf16* As = (bf16*)(dsm + buf * P_STAGE_B);
        bf16* Bs = (bf16*)(dsm + buf * P_STAGE_B + 64 * P_AS_STR * 2);
        int k0 = it * 32;
        #pragma unroll
        for (int t = 0; t < 2; t++) {               // A: 64x32 = 256 chunks
            int idx = tid + t * 128;
            int r = idx >> 2, c = (idx & 3) * 8;
            __pipeline_memcpy_async(As + r * P_AS_STR + c,
                                    Abase + (size_t)r * K + k0 + c, 16);
        }
        #pragma unroll
        for (int t = 0; t < 8; t++) {               // B: 32x256 = 1024 chunks
            int idx = tid + t * 128;
            int r = idx >> 5, c = (idx & 31) * 8;
            __pipeline_memcpy_async(Bs + r * P_BS_STR + c,
                                    W + (size_t)(k0 + r) * 256 + c, 16);
        }
        __pipeline_commit();
    };

    issue(0);
    issue(1);

    for (int it = 0; it < NIT; it++) {
        if (NIT - 1 - it >= 1) __pipeline_wait_prior(1);
        else                   __pipeline_wait_prior(0);
        __syncthreads();

        const bf16* As = (const bf16*)(dsm + (it % 3) * P_STAGE_B);
        const bf16* Bs = (const bf16*)(dsm + (it % 3) * P_STAGE_B + 64 * P_AS_STR * 2);
        #pragma unroll
        for (int kk = 0; kk < 32; kk += 16) {
            wmma::fragment<wmma::matrix_a, 16, 16, 16, bf16, wmma::row_major> af[4];
            wmma::fragment<wmma::matrix_b, 16, 16, 16, bf16, wmma::row_major> bf[4];
            #pragma unroll
            for (int mf = 0; mf < 4; mf++)
                wmma::load_matrix_sync(af[mf], As + (mf * 16) * P_AS_STR + kk, P_AS_STR);
            #pragma unroll
            for (int nf = 0; nf < 4; nf++)
                wmma::load_matrix_sync(bf[nf], Bs + kk * P_BS_STR + wn * 64 + nf * 16, P_BS_STR);
            #pragma unroll
            for (int mf = 0; mf < 4; mf++)
                #pragma unroll
                for (int nf = 0; nf < 4; nf++)
                    wmma::mma_sync(acc[mf][nf], af[mf], bf[nf], acc[mf][nf]);
        }
        if (it + 2 < NIT) issue(it + 2);
    }
    __syncthreads();

    // ---- epilogue: 64x256 fp32 in smem (64KB <= 66KB) ----
    float* epi = (float*)dsm;
    #pragma unroll
    for (int mf = 0; mf < 4; mf++)
        #pragma unroll
        for (int nf = 0; nf < 4; nf++)
            wmma::store_matrix_sync(epi + (mf * 16) * 256 + wn * 64 + nf * 16,
                                    acc[mf][nf], 256, wmma::mem_row_major);
    __syncthreads();

    int b = (bm >> 12);
    const float* gm = g_ada + b * 1536 + 512;

    // pass 1: residual+gate -> g_x1[perm]; keep fp32 result in epi
    #pragma unroll
    for (int t = 0; t < 16; t++) {
        int ch = tid + t * 128;           // 2048 chunks of 8 cols
        int r = ch >> 5;
        int c8 = (ch & 31) * 8;
        int row = bm + r;
        int tt = row & 63, widx = (row >> 6) & 63;
        int wh = (widx >> 3) & 7, ww = widx & 7;
        int pr = (wh * 8 + (tt >> 3) + 4) & 63;
        int pc = (ww * 8 + (tt & 7) + 4) & 63;
        size_t prow = (size_t)(b * 4096 + pr * 64 + pc);

        float v[8];
        *(float4*)(v)     = *(const float4*)(epi + r * 256 + c8);
        *(float4*)(v + 4) = *(const float4*)(epi + r * 256 + c8 + 4);
        float o[8];
        #pragma unroll
        for (int j = 0; j < 8; j++) {
            float val = v[j] + __ldg(&bias[c8 + j]);
            o[j] = __ldg(&xres[prow * 256 + c8 + j]) + gm[c8 + j] * val;
        }
        *(float4*)(g_x1 + prow * 256 + c8)     = *(float4*)(o);
        *(float4*)(g_x1 + prow * 256 + c8 + 4) = *(float4*)(o + 4);
        *(float4*)(epi + r * 256 + c8)     = *(float4*)(o);
        *(float4*)(epi + r * 256 + c8 + 4) = *(float4*)(o + 4);
    }
    __syncthreads();

    // pass 2: LN2 + modulation -> g_h2h[perm]  (one warp per token row)
    const float* cp = g_ada + b * 1536 + 1024;
    const float* sp = g_ada + b * 1536 + 768;
    for (int rr = 0; rr < 16; rr++) {
        int r = wid * 16 + rr;
        int row = bm + r;
        int tt = row & 63, widx = (row >> 6) & 63;
        int wh = (widx >> 3) & 7, ww = widx & 7;
        int pr = (wh * 8 + (tt >> 3) + 4) & 63;
        int pc = (ww * 8 + (tt & 7) + 4) & 63;
        size_t prow = (size_t)(b * 4096 + pr * 64 + pc);

        int ch = lane * 8;
        float4 v0 = *(const float4*)(epi + r * 256 + ch);
        float4 v1 = *(const float4*)(epi + r * 256 + ch + 4);
        float e[8] = {v0.x, v0.y, v0.z, v0.w, v1.x, v1.y, v1.z, v1.w};

        float s = 0.f, q = 0.f;
        #pragma unroll
        for (int j = 0; j < 8; j++) { s += e[j]; q += e[j] * e[j]; }
        #pragma unroll
        for (int off = 16; off > 0; off >>= 1) {
            s += __shfl_xor_sync(0xffffffffu, s, off);
            q += __shfl_xor_sync(0xffffffffu, q, off);
        }
        float mean = s * (1.0f / 256.0f);
        float var  = q * (1.0f / 256.0f) - mean * mean;
        float rstd = rsqrtf(var + 1e-5f);

        float o[8];
        #pragma unroll
        for (int j = 0; j < 8; j++) {
            float y = (e[j] - mean) * rstd * __ldg(&gamma[ch + j]) + __ldg(&beta[ch + j]);
            o[j] = y * (1.0f + cp[ch + j]) + sp[ch + j];
        }
        uint4 u;
        u.x = packbf(o[0], o[1]); u.y = packbf(o[2], o[3]);
        u.z = packbf(o[4], o[5]); u.w = packbf(o[6], o[7]);
        *(uint4*)(g_h2h + prow * 256 + ch) = u;
    }
}

// ---------------------------------------------------------------------------
extern "C" void kernel_launch(void* const* d_in, const int* in_sizes, int n_in,
                              void* d_out, int out_size) {
    const float* x       = (const float*)d_in[0];
    const float* cond    = (const float*)d_in[1];
    const float* norm1_g = (const float*)d_in[2];
    const float* norm1_b = (const float*)d_in[3];
    const float* w_qkv   = (const float*)d_in[4];
    const float* b_qkv   = (const float*)d_in[5];
    const float* rel_b   = (const float*)d_in[6];
    const float* w_proj  = (const float*)d_in[7];
    const float* b_proj  = (const float*)d_in[8];
    const float* norm2_g = (const float*)d_in[9];
    const float* norm2_b = (const float*)d_in[10];
    const float* w_fc1   = (const float*)d_in[11];
    const float* b_fc1   = (const float*)d_in[12];
    const float* w_fc2   = (const float*)d_in[13];
    const float* b_fc2   = (const float*)d_in[14];
    const float* w_ada   = (const float*)d_in[15];
    const float* b_ada   = (const float*)d_in[16];
    float* out = (float*)d_out;

    cudaFuncSetAttribute(gemm_bf16<0>, cudaFuncAttributeMaxDynamicSharedMemorySize, GEMM_SMEM);
    cudaFuncSetAttribute(gemm_bf16<2>, cudaFuncAttributeMaxDynamicSharedMemorySize, GEMM_SMEM);
    cudaFuncSetAttribute(gemm_bf16<3>, cudaFuncAttributeMaxDynamicSharedMemorySize, GEMM_SMEM);
    cudaFuncSetAttribute(gemm_proj_ln, cudaFuncAttributeMaxDynamicSharedMemorySize, P_GEMM_SMEM);

    cvt_all_kernel<<<768, 256>>>(w_qkv, w_proj, w_fc1, w_fc2);
    ada_kernel<<<16, 256>>>(cond, w_ada, b_ada);
    ln_mod0_kernel<<<8192, 256>>>(x, norm1_g, norm1_b);
    gemm_bf16<0><<<dim3(6, 512), 128, GEMM_SMEM>>>(b_qkv, nullptr);
    attn_wmma_kernel<<<dim3(1024, 8), 128>>>(rel_b);
    gemm_proj_ln<<<1024, 128, P_GEMM_SMEM>>>(b_proj, x, norm2_g, norm2_b);
    gemm_bf16<2><<<dim3(8, 512), 128, GEMM_SMEM>>>(b_fc1, nullptr);
    gemm_bf16<3><<<dim3(2, 512), 128, GEMM_SMEM>>>(b_fc2, out);
}